// round 7
// baseline (speedup 1.0000x reference)
#include <cuda_runtime.h>
#include <cuda_bf16.h>
#include <cstdint>

#define Bsz 2
#define S   2048
#define D   1024
#define H   16
#define HD  64
#define EPSV 1e-8f

// ---------------- scratch (__device__ globals; alloc-free rule) -------------
__device__ __nv_bfloat16 g_xh[(size_t)Bsz * S * D];
__device__ __nv_bfloat16 g_xl[(size_t)Bsz * S * D];
__device__ __nv_bfloat16 g_w1h[(size_t)2 * D * D];
__device__ __nv_bfloat16 g_w1l[(size_t)2 * D * D];
__device__ __nv_bfloat16 g_w3h[(size_t)D * D];
__device__ __nv_bfloat16 g_w3l[(size_t)D * D];
__device__ __nv_bfloat16 g_qkh[(size_t)Bsz * S * 2 * D];  // stage1 out hi (Q pre-scaled)
__device__ __nv_bfloat16 g_qkl[(size_t)Bsz * S * 2 * D];  // stage1 out lo
__device__ __nv_bfloat16 g_vbh[(size_t)Bsz * S * D];      // V bf16 hi
__device__ __nv_bfloat16 g_vbl[(size_t)Bsz * S * D];      // V bf16 lo
__device__ __nv_bfloat16 g_ath[(size_t)Bsz * S * D];      // attention out hi
__device__ __nv_bfloat16 g_atl[(size_t)Bsz * S * D];      // attention out lo

// ---------------- helpers (all plain sm_80+ PTX; no 'a' features) -----------
__device__ __forceinline__ uint32_t smem_u32(const void* p) {
    uint32_t a;
    asm("{ .reg .u64 t; cvta.to.shared.u64 t, %1; cvt.u32.u64 %0, t; }" : "=r"(a) : "l"(p));
    return a;
}
__device__ __forceinline__ void cp16(uint32_t dst, const void* src) {
    asm volatile("cp.async.cg.shared.global [%0], [%1], 16;" :: "r"(dst), "l"(src));
}
__device__ __forceinline__ void cp_commit() {
    asm volatile("cp.async.commit_group;" ::: "memory");
}
__device__ __forceinline__ void cp_wait0() {
    asm volatile("cp.async.wait_group 0;" ::: "memory");
}
__device__ __forceinline__ void cp_wait1() {
    asm volatile("cp.async.wait_group 1;" ::: "memory");
}
__device__ __forceinline__ void ldsm_x4(uint32_t (&r)[4], uint32_t addr) {
    asm volatile("ldmatrix.sync.aligned.m8n8.x4.shared.b16 {%0,%1,%2,%3}, [%4];"
                 : "=r"(r[0]), "=r"(r[1]), "=r"(r[2]), "=r"(r[3]) : "r"(addr));
}
__device__ __forceinline__ void ldsm_x4_t(uint32_t (&r)[4], uint32_t addr) {
    asm volatile("ldmatrix.sync.aligned.m8n8.x4.trans.shared.b16 {%0,%1,%2,%3}, [%4];"
                 : "=r"(r[0]), "=r"(r[1]), "=r"(r[2]), "=r"(r[3]) : "r"(addr));
}
__device__ __forceinline__ void mma16816(float (&c)[4], const uint32_t (&a)[4],
                                         uint32_t b0, uint32_t b1) {
    asm volatile(
        "mma.sync.aligned.m16n8k16.row.col.f32.bf16.bf16.f32 "
        "{%0,%1,%2,%3}, {%4,%5,%6,%7}, {%8,%9}, {%0,%1,%2,%3};"
        : "+f"(c[0]), "+f"(c[1]), "+f"(c[2]), "+f"(c[3])
        : "r"(a[0]), "r"(a[1]), "r"(a[2]), "r"(a[3]), "r"(b0), "r"(b1));
}
__device__ __forceinline__ uint32_t bf2pack(float lo, float hi) {
    uint32_t r;
    asm("cvt.rn.bf16x2.f32 %0, %1, %2;" : "=r"(r) : "f"(hi), "f"(lo));
    return r;
}
__device__ __forceinline__ void split_store(__nv_bfloat16* Oh, __nv_bfloat16* Ol,
                                            size_t idx, float v0, float v1) {
    __nv_bfloat16 h0 = __float2bfloat16(v0), h1 = __float2bfloat16(v1);
    __nv_bfloat162 hp; hp.x = h0; hp.y = h1;
    __nv_bfloat162 lp;
    lp.x = __float2bfloat16(v0 - __bfloat162float(h0));
    lp.y = __float2bfloat16(v1 - __bfloat162float(h1));
    *(__nv_bfloat162*)(Oh + idx) = hp;
    *(__nv_bfloat162*)(Ol + idx) = lp;
}

// ---------------------------------------------------------------------------
// Fused split-precision conversion: x, in_proj_w[0:2D], out_w, V in one grid.
// ---------------------------------------------------------------------------
#define CN1 1048576   // x       float4s
#define CN2 524288    // w1
#define CN3 262144    // w3
#define CN4 1048576   // V
#define CNT (CN1 + CN2 + CN3 + CN4)

__global__ __launch_bounds__(256)
void conv_all(const float* __restrict__ x, const float* __restrict__ w1,
              const float* __restrict__ w3, const float* __restrict__ Vin) {
    int i = blockIdx.x * 256 + threadIdx.x;
    if (i >= CNT) return;
    const float* src;
    __nv_bfloat16 *hi, *lo;
    int j = i;
    if (j < CN1) { src = x; hi = g_xh; lo = g_xl; }
    else if ((j -= CN1) < CN2) { src = w1; hi = g_w1h; lo = g_w1l; }
    else if ((j -= CN2) < CN3) { src = w3; hi = g_w3h; lo = g_w3l; }
    else { j -= CN3; src = Vin; hi = g_vbh; lo = g_vbl; }
    float4 v = *(const float4*)(src + (size_t)j * 4);
    split_store(hi, lo, (size_t)j * 4, v.x, v.y);
    split_store(hi, lo, (size_t)j * 4 + 2, v.z, v.w);
}

// ---------------------------------------------------------------------------
// mma.sync bf16x3 GEMM: C = (Ah+Al)[M][K] * (Bh+Bl)[N][K]^T + bias
// 128x128 tile, BK=32, cp.async double-buffered. 8 warps (2x4), each 64x32.
// mode 0: fp32 out to Cf. mode 1: bf16 hi/lo split out, Q cols scaled 0.125.
// ---------------------------------------------------------------------------
#define GEMM_SMEM (2 * 20480 * 2)   // 2 buffers x 20480 halves

__device__ __forceinline__ void gemm_issue(
    const __nv_bfloat16* Ah, const __nv_bfloat16* Al,
    const __nv_bfloat16* Bh, const __nv_bfloat16* Bl,
    int K, int row0, int col0, int chunk, uint32_t dstbase, int tid) {
    #pragma unroll
    for (int j = 0; j < 8; j++) {
        int linear = tid + j * 256;
        int arr = linear >> 9, rem = linear & 511;
        int r = rem >> 2, c = rem & 3;
        const __nv_bfloat16* src = (arr == 0) ? Ah : (arr == 1) ? Al : (arr == 2) ? Bh : Bl;
        int grow = ((arr < 2) ? row0 : col0) + r;
        cp16(dstbase + (uint32_t)(arr * 5120 + r * 40 + c * 8) * 2,
             src + (size_t)grow * K + chunk * 32 + c * 8);
    }
}

__global__ __launch_bounds__(256, 2)
void mma_gemm(const __nv_bfloat16* __restrict__ Ah, const __nv_bfloat16* __restrict__ Al,
              const __nv_bfloat16* __restrict__ Bh, const __nv_bfloat16* __restrict__ Bl,
              const float* __restrict__ bias, float* __restrict__ Cf,
              __nv_bfloat16* __restrict__ Oh, __nv_bfloat16* __restrict__ Ol,
              int K, int N, int mode) {
    extern __shared__ __nv_bfloat16 smem[];
    const int tid = threadIdx.x;
    const int wid = tid >> 5, lane = tid & 31;
    const int wr = wid >> 2, wc = wid & 3;
    const int row0 = blockIdx.y * 128, col0 = blockIdx.x * 128;
    const uint32_t sb = smem_u32(smem);

    float acc[4][4][4] = {};

    gemm_issue(Ah, Al, Bh, Bl, K, row0, col0, 0, sb, tid);
    cp_commit();

    const int nch = K / 32;
    for (int ch = 0; ch < nch; ++ch) {
        const int p = ch & 1;
        if (ch + 1 < nch) {
            gemm_issue(Ah, Al, Bh, Bl, K, row0, col0, ch + 1, sb + (p ^ 1) * 40960, tid);
            cp_commit();
            cp_wait1();
        } else {
            cp_wait0();
        }
        __syncthreads();

        const uint32_t bufb = sb + p * 40960;
        #pragma unroll
        for (int t = 0; t < 3; t++) {
            const uint32_t aoff = (t == 2) ? 5120u : 0u;
            const uint32_t boff = (t == 1) ? 15360u : 10240u;
            #pragma unroll
            for (int kk = 0; kk < 2; kk++) {
                uint32_t a[4][4];
                #pragma unroll
                for (int i = 0; i < 4; i++)
                    ldsm_x4(a[i], bufb + (aoff + (uint32_t)((wr * 64 + i * 16 + (lane & 15)) * 40
                                                  + kk * 16 + (lane >> 4) * 8)) * 2);
                #pragma unroll
                for (int jp = 0; jp < 2; jp++) {
                    uint32_t r4[4];
                    ldsm_x4(r4, bufb + (boff + (uint32_t)((wc * 32 + jp * 16 + (lane & 15)) * 40
                                                  + kk * 16 + (lane >> 4) * 8)) * 2);
                    #pragma unroll
                    for (int i = 0; i < 4; i++) {
                        mma16816(acc[i][jp * 2 + 0], a[i], r4[0], r4[2]);
                        mma16816(acc[i][jp * 2 + 1], a[i], r4[1], r4[3]);
                    }
                }
            }
        }
        __syncthreads();
    }

    // epilogue (mode 1: Q columns pre-scaled by 1/sqrt(HD); col block uniform)
    const float qs = (mode == 1 && col0 < D) ? 0.125f : 1.0f;
    #pragma unroll
    for (int j = 0; j < 4; j++) {
        const int col = col0 + wc * 32 + j * 8 + (lane & 3) * 2;
        const float b0 = bias[col], b1 = bias[col + 1];
        #pragma unroll
        for (int i = 0; i < 4; i++) {
            const int row = row0 + wr * 64 + i * 16 + (lane >> 2);
            float v0 = (acc[i][j][0] + b0) * qs, v1 = (acc[i][j][1] + b1) * qs;
            float w0 = (acc[i][j][2] + b0) * qs, w1 = (acc[i][j][3] + b1) * qs;
            if (mode == 0) {
                *(float2*)(Cf + (size_t)row * N + col) = make_float2(v0, v1);
                *(float2*)(Cf + (size_t)(row + 8) * N + col) = make_float2(w0, w1);
            } else {
                split_store(Oh, Ol, (size_t)row * N + col, v0, v1);
                split_store(Oh, Ol, (size_t)(row + 8) * N + col, w0, w1);
            }
        }
    }
}

// ---------------------------------------------------------------------------
// Attention via mma.sync. Per CTA: 128 q rows, (b,h) from grid; 8 warps x 16q.
// Scores = 3-term bf16 split (QhKh + QlKh + QhKl) with register-cached Q frags;
// PV = 3-term split (PhVh + PlVh + PhVl) with register-cached V frags.
// 3-deep KV ring -> single barrier per iteration.
// Single pass: Z, Zm, O accumulate; out = O / (Zm + EPS*Z).
// ---------------------------------------------------------------------------
// smem halves: Qh@0 (128*72), Ql@9216, 3 KV buffers @18432 (stride 18432)
//   per buf: Kh@0, Kl@4608, Vh@9216, Vl@13824
#define ATTN_SMEM ((18432 + 3 * 18432) * 2)

__device__ __forceinline__ void attn_issue_kv(int b, int h, int it, uint32_t sb,
                                              int p, int tid) {
    const int k0 = it * 64;
    #pragma unroll
    for (int j = 0; j < 8; j++) {
        int linear = tid + j * 256;
        int arr = linear >> 9, rem = linear & 511;
        int r = rem >> 3, c = rem & 7;
        const __nv_bfloat16* src;
        if (arr == 0)      src = g_qkh + (size_t)(b * S + k0 + r) * 2048 + D + h * 64 + c * 8;
        else if (arr == 1) src = g_qkl + (size_t)(b * S + k0 + r) * 2048 + D + h * 64 + c * 8;
        else if (arr == 2) src = g_vbh + (size_t)(b * S + k0 + r) * 1024 + h * 64 + c * 8;
        else               src = g_vbl + (size_t)(b * S + k0 + r) * 1024 + h * 64 + c * 8;
        cp16(sb + (uint32_t)(18432 + p * 18432 + arr * 4608 + r * 72 + c * 8) * 2, src);
    }
}

__global__ __launch_bounds__(256)
void attn_mma(const float* __restrict__ Min) {
    extern __shared__ __nv_bfloat16 smem[];
    const int tid = threadIdx.x;
    const int wid = tid >> 5, lane = tid & 31;
    const int b = blockIdx.z, h = blockIdx.y;
    const int q0 = blockIdx.x * 128;
    const uint32_t sb = smem_u32(smem);

    // Q hi/lo -> smem (group 0 together with iter-0 K/V)
    #pragma unroll
    for (int j = 0; j < 8; j++) {
        int linear = tid + j * 256;
        int arr = linear >> 10, rem = linear & 1023;
        int r = rem >> 3, c = rem & 7;
        const __nv_bfloat16* src = (arr ? g_qkl : g_qkh)
            + (size_t)(b * S + q0 + r) * 2048 + h * 64 + c * 8;
        cp16(sb + (uint32_t)(arr * 9216 + r * 72 + c * 8) * 2, src);
    }
    attn_issue_kv(b, h, 0, sb, 0, tid);
    cp_commit();

    float Oc[8][4] = {};
    float z0 = 0.f, z1 = 0.f, zm0 = 0.f, zm1 = 0.f;
    int p = 0;

    const uint32_t qrow_off = (uint32_t)((wid * 16 + (lane & 15)) * 72 + (lane >> 4) * 8);

    const int niter = S / 64;
    for (int it = 0; it < niter; ++it) {
        if (it + 1 < niter) {
            int pn = (it + 1 == 3 * ((it + 1) / 3)) ? 0 : ((it + 1) - 3 * ((it + 1) / 3));
            pn = (p + 1 == 3) ? 0 : p + 1;
            attn_issue_kv(b, h, it + 1, sb, pn, tid);
            cp_commit();
            cp_wait1();
        } else {
            cp_wait0();
        }

        // mask prefetch (global; independent of smem) before the barrier
        const float* mb = Min + ((size_t)(b * S + q0 + wid * 16 + (lane >> 2))) * S
                          + it * 64 + (lane & 3) * 2;
        float2 m0[8], m1[8];
        #pragma unroll
        for (int j = 0; j < 8; j++) {
            m0[j] = *(const float2*)(mb + j * 8);
            m1[j] = *(const float2*)(mb + (size_t)8 * S + j * 8);
        }

        __syncthreads();   // KV buffer p ready; 3-deep ring makes this the only barrier

        const uint32_t kvb = 18432u + (uint32_t)p * 18432u;

        // cache Q frags (hi+lo) in registers
        uint32_t qh[4][4], ql[4][4];
        #pragma unroll
        for (int kk = 0; kk < 4; kk++) {
            ldsm_x4(qh[kk], sb + (qrow_off + (uint32_t)(kk * 16)) * 2);
            ldsm_x4(ql[kk], sb + (9216u + qrow_off + (uint32_t)(kk * 16)) * 2);
        }

        // scores: 3-term split, K frags loaded once each
        float sc[8][4] = {};
        #pragma unroll
        for (int jp = 0; jp < 4; jp++) {
            const uint32_t krow = (uint32_t)((jp * 16 + (lane & 15)) * 72 + (lane >> 4) * 8);
            #pragma unroll
            for (int kk = 0; kk < 4; kk++) {
                uint32_t kh[4];
                ldsm_x4(kh, sb + (kvb + krow + (uint32_t)(kk * 16)) * 2);
                mma16816(sc[jp * 2 + 0], qh[kk], kh[0], kh[2]);
                mma16816(sc[jp * 2 + 1], qh[kk], kh[1], kh[3]);
                mma16816(sc[jp * 2 + 0], ql[kk], kh[0], kh[2]);
                mma16816(sc[jp * 2 + 1], ql[kk], kh[1], kh[3]);
                uint32_t kl[4];
                ldsm_x4(kl, sb + (kvb + 4608u + krow + (uint32_t)(kk * 16)) * 2);
                mma16816(sc[jp * 2 + 0], qh[kk], kl[0], kl[2]);
                mma16816(sc[jp * 2 + 1], qh[kk], kl[1], kl[3]);
            }
        }

        // exp + mask + sums + repack P (split hi/lo) into a-frags
        uint32_t pah[4][4], pal[4][4];
        #pragma unroll
        for (int j = 0; j < 8; j++) {
            float e0 = __expf(sc[j][0]);
            float e1 = __expf(sc[j][1]);
            float e2 = __expf(sc[j][2]);
            float e3 = __expf(sc[j][3]);
            z0 += e0 + e1; z1 += e2 + e3;
            float em0 = e0 * m0[j].x, em1 = e1 * m0[j].y;
            float em2 = e2 * m1[j].x, em3 = e3 * m1[j].y;
            zm0 += em0 + em1; zm1 += em2 + em3;
            float h0 = __bfloat162float(__float2bfloat16(em0));
            float h1 = __bfloat162float(__float2bfloat16(em1));
            float h2 = __bfloat162float(__float2bfloat16(em2));
            float h3 = __bfloat162float(__float2bfloat16(em3));
            pah[j >> 1][(j & 1) * 2 + 0] = bf2pack(em0, em1);
            pah[j >> 1][(j & 1) * 2 + 1] = bf2pack(em2, em3);
            pal[j >> 1][(j & 1) * 2 + 0] = bf2pack(em0 - h0, em1 - h1);
            pal[j >> 1][(j & 1) * 2 + 1] = bf2pack(em2 - h2, em3 - h3);
        }

        // PV: 3-term split, V frags loaded once each
        #pragma unroll
        for (int j2 = 0; j2 < 4; j2++) {
            const uint32_t vrow = (uint32_t)((j2 * 16 + ((lane >> 3) & 1) * 8 + (lane & 7)) * 72
                                             + (lane >> 4) * 8);
            #pragma unroll
            for (int ndp = 0; ndp < 4; ndp++) {
                uint32_t vh[4];
                ldsm_x4_t(vh, sb + (kvb + 9216u + vrow + (uint32_t)(ndp * 16)) * 2);
                mma16816(Oc[ndp * 2 + 0], pah[j2], vh[0], vh[1]);
                mma16816(Oc[ndp * 2 + 1], pah[j2], vh[2], vh[3]);
                mma16816(Oc[ndp * 2 + 0], pal[j2], vh[0], vh[1]);
                mma16816(Oc[ndp * 2 + 1], pal[j2], vh[2], vh[3]);
                uint32_t vl[4];
                ldsm_x4_t(vl, sb + (kvb + 13824u + vrow + (uint32_t)(ndp * 16)) * 2);
                mma16816(Oc[ndp * 2 + 0], pah[j2], vl[0], vl[1]);
                mma16816(Oc[ndp * 2 + 1], pah[j2], vl[2], vl[3]);
            }
        }
        p = (p + 1 == 3) ? 0 : p + 1;
    }

    // quad reduce (lanes sharing lane>>2 hold the same rows)
    #pragma unroll
    for (int off = 1; off < 4; off <<= 1) {
        z0  += __shfl_xor_sync(0xffffffffu, z0, off);
        z1  += __shfl_xor_sync(0xffffffffu, z1, off);
        zm0 += __shfl_xor_sync(0xffffffffu, zm0, off);
        zm1 += __shfl_xor_sync(0xffffffffu, zm1, off);
    }
    const float inv0 = 1.0f / (zm0 + EPSV * z0);
    const float inv1 = 1.0f / (zm1 + EPSV * z1);

    const int row = b * S + q0 + wid * 16 + (lane >> 2);
    #pragma unroll
    for (int nd = 0; nd < 8; nd++) {
        const int col = h * 64 + nd * 8 + (lane & 3) * 2;
        split_store(g_ath, g_atl, (size_t)row * D + col,
                    Oc[nd][0] * inv0, Oc[nd][1] * inv0);
        split_store(g_ath, g_atl, (size_t)(row + 8) * D + col,
                    Oc[nd][2] * inv1, Oc[nd][3] * inv1);
    }
}

// ---------------------------------------------------------------------------
extern "C" void kernel_launch(void* const* d_in, const int* in_sizes, int n_in,
                              void* d_out, int out_size) {
    const float* x         = (const float*)d_in[0];  // [B,S,D]
    const float* Vin       = (const float*)d_in[1];  // [B,S,H,HD]
    const float* Min       = (const float*)d_in[2];  // [B,S,S]
    const float* in_proj_w = (const float*)d_in[3];  // [3D,D]
    const float* in_proj_b = (const float*)d_in[4];  // [3D]
    const float* out_w     = (const float*)d_in[5];  // [D,D]
    const float* out_b     = (const float*)d_in[6];  // [D]
    float* out             = (float*)d_out;          // [B,S,D]

    __nv_bfloat16 *xh, *xl, *w1h, *w1l, *w3h, *w3l, *qkh, *qkl, *ath, *atl;
    cudaGetSymbolAddress((void**)&xh,  g_xh);
    cudaGetSymbolAddress((void**)&xl,  g_xl);
    cudaGetSymbolAddress((void**)&w1h, g_w1h);
    cudaGetSymbolAddress((void**)&w1l, g_w1l);
    cudaGetSymbolAddress((void**)&w3h, g_w3h);
    cudaGetSymbolAddress((void**)&w3l, g_w3l);
    cudaGetSymbolAddress((void**)&qkh, g_qkh);
    cudaGetSymbolAddress((void**)&qkl, g_qkl);
    cudaGetSymbolAddress((void**)&ath, g_ath);
    cudaGetSymbolAddress((void**)&atl, g_atl);

    cudaFuncSetAttribute(mma_gemm, cudaFuncAttributeMaxDynamicSharedMemorySize, GEMM_SMEM);
    cudaFuncSetAttribute(attn_mma, cudaFuncAttributeMaxDynamicSharedMemorySize, ATTN_SMEM);

    const int Mtot = Bsz * S;  // 4096

    // fused conversions (bf16 hi/lo splits for x, w1, w3, V)
    conv_all<<<(CNT + 255) / 256, 256>>>(x, in_proj_w, out_w, Vin);

    // Stage 1: [Q|K] = x @ in_proj_w[0:2D]^T + b -> bf16 hi/lo, Q scaled 1/8
    mma_gemm<<<dim3((2 * D) / 128, Mtot / 128), 256, GEMM_SMEM>>>(
        xh, xl, w1h, w1l, in_proj_b, nullptr, qkh, qkl, D, 2 * D, 1);

    // Stage 2: masked-renormalized attention -> bf16 hi/lo [4096][1024]
    attn_mma<<<dim3(S / 128, H, Bsz), 256, ATTN_SMEM>>>(Min);

    // Stage 3: out = attn @ out_w^T + out_b  (fp32)
    mma_gemm<<<dim3(D / 128, Mtot / 128), 256, GEMM_SMEM>>>(
        ath, atl, w3h, w3l, out_b, out, nullptr, nullptr, D, D, 0);
}

// round 8
// speedup vs baseline: 1.1334x; 1.1334x over previous
#include <cuda_runtime.h>
#include <cuda_bf16.h>
#include <cstdint>

#define Bsz 2
#define S   2048
#define D   1024
#define H   16
#define HD  64
#define EPSV 1e-8f

// ---------------- scratch (__device__ globals; alloc-free rule) -------------
__device__ __nv_bfloat16 g_xh[(size_t)Bsz * S * D];
__device__ __nv_bfloat16 g_xl[(size_t)Bsz * S * D];
__device__ __nv_bfloat16 g_w1h[(size_t)2 * D * D];
__device__ __nv_bfloat16 g_w1l[(size_t)2 * D * D];
__device__ __nv_bfloat16 g_w3h[(size_t)D * D];
__device__ __nv_bfloat16 g_w3l[(size_t)D * D];
__device__ __nv_bfloat16 g_qkh[(size_t)Bsz * S * 2 * D];  // stage1 out hi (Q pre-scaled)
__device__ __nv_bfloat16 g_qkl[(size_t)Bsz * S * 2 * D];  // stage1 out lo
__device__ __nv_bfloat16 g_vbh[(size_t)Bsz * S * D];      // V bf16 hi
__device__ __nv_bfloat16 g_vbl[(size_t)Bsz * S * D];      // V bf16 lo
__device__ __nv_bfloat16 g_ath[(size_t)Bsz * S * D];      // attention out hi
__device__ __nv_bfloat16 g_atl[(size_t)Bsz * S * D];      // attention out lo

// ---------------- helpers (all plain sm_80+ PTX; no 'a' features) -----------
__device__ __forceinline__ uint32_t smem_u32(const void* p) {
    uint32_t a;
    asm("{ .reg .u64 t; cvta.to.shared.u64 t, %1; cvt.u32.u64 %0, t; }" : "=r"(a) : "l"(p));
    return a;
}
__device__ __forceinline__ void cp16(uint32_t dst, const void* src) {
    asm volatile("cp.async.cg.shared.global [%0], [%1], 16;" :: "r"(dst), "l"(src));
}
__device__ __forceinline__ void cp_commit() {
    asm volatile("cp.async.commit_group;" ::: "memory");
}
__device__ __forceinline__ void cp_wait0() {
    asm volatile("cp.async.wait_group 0;" ::: "memory");
}
__device__ __forceinline__ void cp_wait1() {
    asm volatile("cp.async.wait_group 1;" ::: "memory");
}
__device__ __forceinline__ void ldsm_x4(uint32_t (&r)[4], uint32_t addr) {
    asm volatile("ldmatrix.sync.aligned.m8n8.x4.shared.b16 {%0,%1,%2,%3}, [%4];"
                 : "=r"(r[0]), "=r"(r[1]), "=r"(r[2]), "=r"(r[3]) : "r"(addr));
}
__device__ __forceinline__ void ldsm_x4_t(uint32_t (&r)[4], uint32_t addr) {
    asm volatile("ldmatrix.sync.aligned.m8n8.x4.trans.shared.b16 {%0,%1,%2,%3}, [%4];"
                 : "=r"(r[0]), "=r"(r[1]), "=r"(r[2]), "=r"(r[3]) : "r"(addr));
}
__device__ __forceinline__ void mma16816(float (&c)[4], const uint32_t (&a)[4],
                                         uint32_t b0, uint32_t b1) {
    asm volatile(
        "mma.sync.aligned.m16n8k16.row.col.f32.bf16.bf16.f32 "
        "{%0,%1,%2,%3}, {%4,%5,%6,%7}, {%8,%9}, {%0,%1,%2,%3};"
        : "+f"(c[0]), "+f"(c[1]), "+f"(c[2]), "+f"(c[3])
        : "r"(a[0]), "r"(a[1]), "r"(a[2]), "r"(a[3]), "r"(b0), "r"(b1));
}
__device__ __forceinline__ uint32_t bf2pack(float lo, float hi) {
    uint32_t r;
    asm("cvt.rn.bf16x2.f32 %0, %1, %2;" : "=r"(r) : "f"(hi), "f"(lo));
    return r;
}
__device__ __forceinline__ void split_store(__nv_bfloat16* Oh, __nv_bfloat16* Ol,
                                            size_t idx, float v0, float v1) {
    __nv_bfloat16 h0 = __float2bfloat16(v0), h1 = __float2bfloat16(v1);
    __nv_bfloat162 hp; hp.x = h0; hp.y = h1;
    __nv_bfloat162 lp;
    lp.x = __float2bfloat16(v0 - __bfloat162float(h0));
    lp.y = __float2bfloat16(v1 - __bfloat162float(h1));
    *(__nv_bfloat162*)(Oh + idx) = hp;
    *(__nv_bfloat162*)(Ol + idx) = lp;
}

// ---------------------------------------------------------------------------
// Fused split-precision conversion: x, in_proj_w[0:2D], out_w, V in one grid.
// ---------------------------------------------------------------------------
#define CN1 1048576   // x       float4s
#define CN2 524288    // w1
#define CN3 262144    // w3
#define CN4 1048576   // V
#define CNT (CN1 + CN2 + CN3 + CN4)

__global__ __launch_bounds__(256)
void conv_all(const float* __restrict__ x, const float* __restrict__ w1,
              const float* __restrict__ w3, const float* __restrict__ Vin) {
    int i = blockIdx.x * 256 + threadIdx.x;
    if (i >= CNT) return;
    const float* src;
    __nv_bfloat16 *hi, *lo;
    int j = i;
    if (j < CN1) { src = x; hi = g_xh; lo = g_xl; }
    else if ((j -= CN1) < CN2) { src = w1; hi = g_w1h; lo = g_w1l; }
    else if ((j -= CN2) < CN3) { src = w3; hi = g_w3h; lo = g_w3l; }
    else { j -= CN3; src = Vin; hi = g_vbh; lo = g_vbl; }
    float4 v = *(const float4*)(src + (size_t)j * 4);
    split_store(hi, lo, (size_t)j * 4, v.x, v.y);
    split_store(hi, lo, (size_t)j * 4 + 2, v.z, v.w);
}

// ---------------------------------------------------------------------------
// mma.sync bf16x3 GEMM: C = (Ah+Al)[M][K] * (Bh+Bl)[N][K]^T + bias
// 128x128 tile, BK=32, cp.async double-buffered. 8 warps (2x4), each 64x32.
// mode 0: fp32 out to Cf. mode 1: bf16 hi/lo split out, Q cols scaled 0.125.
// ---------------------------------------------------------------------------
#define GEMM_SMEM (2 * 20480 * 2)   // 2 buffers x 20480 halves

__device__ __forceinline__ void gemm_issue(
    const __nv_bfloat16* Ah, const __nv_bfloat16* Al,
    const __nv_bfloat16* Bh, const __nv_bfloat16* Bl,
    int K, int row0, int col0, int chunk, uint32_t dstbase, int tid) {
    #pragma unroll
    for (int j = 0; j < 8; j++) {
        int linear = tid + j * 256;
        int arr = linear >> 9, rem = linear & 511;
        int r = rem >> 2, c = rem & 3;
        const __nv_bfloat16* src = (arr == 0) ? Ah : (arr == 1) ? Al : (arr == 2) ? Bh : Bl;
        int grow = ((arr < 2) ? row0 : col0) + r;
        cp16(dstbase + (uint32_t)(arr * 5120 + r * 40 + c * 8) * 2,
             src + (size_t)grow * K + chunk * 32 + c * 8);
    }
}

__global__ __launch_bounds__(256, 2)
void mma_gemm(const __nv_bfloat16* __restrict__ Ah, const __nv_bfloat16* __restrict__ Al,
              const __nv_bfloat16* __restrict__ Bh, const __nv_bfloat16* __restrict__ Bl,
              const float* __restrict__ bias, float* __restrict__ Cf,
              __nv_bfloat16* __restrict__ Oh, __nv_bfloat16* __restrict__ Ol,
              int K, int N, int mode) {
    extern __shared__ __nv_bfloat16 smem[];
    const int tid = threadIdx.x;
    const int wid = tid >> 5, lane = tid & 31;
    const int wr = wid >> 2, wc = wid & 3;
    const int row0 = blockIdx.y * 128, col0 = blockIdx.x * 128;
    const uint32_t sb = smem_u32(smem);

    float acc[4][4][4] = {};

    gemm_issue(Ah, Al, Bh, Bl, K, row0, col0, 0, sb, tid);
    cp_commit();

    const int nch = K / 32;
    for (int ch = 0; ch < nch; ++ch) {
        const int p = ch & 1;
        if (ch + 1 < nch) {
            gemm_issue(Ah, Al, Bh, Bl, K, row0, col0, ch + 1, sb + (p ^ 1) * 40960, tid);
            cp_commit();
            cp_wait1();
        } else {
            cp_wait0();
        }
        __syncthreads();

        const uint32_t bufb = sb + p * 40960;
        #pragma unroll
        for (int t = 0; t < 3; t++) {
            const uint32_t aoff = (t == 2) ? 5120u : 0u;
            const uint32_t boff = (t == 1) ? 15360u : 10240u;
            #pragma unroll
            for (int kk = 0; kk < 2; kk++) {
                uint32_t a[4][4];
                #pragma unroll
                for (int i = 0; i < 4; i++)
                    ldsm_x4(a[i], bufb + (aoff + (uint32_t)((wr * 64 + i * 16 + (lane & 15)) * 40
                                                  + kk * 16 + (lane >> 4) * 8)) * 2);
                #pragma unroll
                for (int jp = 0; jp < 2; jp++) {
                    uint32_t r4[4];
                    ldsm_x4(r4, bufb + (boff + (uint32_t)((wc * 32 + jp * 16 + (lane & 15)) * 40
                                                  + kk * 16 + (lane >> 4) * 8)) * 2);
                    #pragma unroll
                    for (int i = 0; i < 4; i++) {
                        mma16816(acc[i][jp * 2 + 0], a[i], r4[0], r4[2]);
                        mma16816(acc[i][jp * 2 + 1], a[i], r4[1], r4[3]);
                    }
                }
            }
        }
        __syncthreads();
    }

    // epilogue (mode 1: Q columns pre-scaled by 1/sqrt(HD); col block uniform)
    const float qs = (mode == 1 && col0 < D) ? 0.125f : 1.0f;
    #pragma unroll
    for (int j = 0; j < 4; j++) {
        const int col = col0 + wc * 32 + j * 8 + (lane & 3) * 2;
        const float b0 = bias[col], b1 = bias[col + 1];
        #pragma unroll
        for (int i = 0; i < 4; i++) {
            const int row = row0 + wr * 64 + i * 16 + (lane >> 2);
            float v0 = (acc[i][j][0] + b0) * qs, v1 = (acc[i][j][1] + b1) * qs;
            float w0 = (acc[i][j][2] + b0) * qs, w1 = (acc[i][j][3] + b1) * qs;
            if (mode == 0) {
                *(float2*)(Cf + (size_t)row * N + col) = make_float2(v0, v1);
                *(float2*)(Cf + (size_t)(row + 8) * N + col) = make_float2(w0, w1);
            } else {
                split_store(Oh, Ol, (size_t)row * N + col, v0, v1);
                split_store(Oh, Ol, (size_t)(row + 8) * N + col, w0, w1);
            }
        }
    }
}

// ---------------------------------------------------------------------------
// Attention via mma.sync. Per CTA: 128 q rows, (b,h) from grid; 8 warps x 16q.
// Scores = 3-term bf16 split (QhKh + QlKh + QhKl); mask as bit-masks in regs
// (M is exactly 0/1, so bit-select == multiply); PV = 3-term split.
// 2 KV buffers (110.6KB smem) + __launch_bounds__(256,2) -> 2 CTAs/SM.
// Single pass: Z, Zm, O accumulate; out = O / (Zm + EPS*Z).
// ---------------------------------------------------------------------------
// smem halves: Qh@0 (128*72), Ql@9216, 2 KV buffers @18432 (stride 18432)
//   per buf: Kh@0, Kl@4608, Vh@9216, Vl@13824
#define ATTN_SMEM ((18432 + 2 * 18432) * 2)

__device__ __forceinline__ void attn_issue_kv(int b, int h, int it, uint32_t sb,
                                              int p, int tid) {
    const int k0 = it * 64;
    #pragma unroll
    for (int j = 0; j < 8; j++) {
        int linear = tid + j * 256;
        int arr = linear >> 9, rem = linear & 511;
        int r = rem >> 3, c = rem & 7;
        const __nv_bfloat16* src;
        if (arr == 0)      src = g_qkh + (size_t)(b * S + k0 + r) * 2048 + D + h * 64 + c * 8;
        else if (arr == 1) src = g_qkl + (size_t)(b * S + k0 + r) * 2048 + D + h * 64 + c * 8;
        else if (arr == 2) src = g_vbh + (size_t)(b * S + k0 + r) * 1024 + h * 64 + c * 8;
        else               src = g_vbl + (size_t)(b * S + k0 + r) * 1024 + h * 64 + c * 8;
        cp16(sb + (uint32_t)(18432 + p * 18432 + arr * 4608 + r * 72 + c * 8) * 2, src);
    }
}

__global__ __launch_bounds__(256, 2)
void attn_mma(const float* __restrict__ Min) {
    extern __shared__ __nv_bfloat16 smem[];
    const int tid = threadIdx.x;
    const int wid = tid >> 5, lane = tid & 31;
    const int b = blockIdx.z, h = blockIdx.y;
    const int q0 = blockIdx.x * 128;
    const uint32_t sb = smem_u32(smem);

    // Q hi/lo -> smem (same commit group as iter-0 K/V)
    #pragma unroll
    for (int j = 0; j < 8; j++) {
        int linear = tid + j * 256;
        int arr = linear >> 10, rem = linear & 1023;
        int r = rem >> 3, c = rem & 7;
        const __nv_bfloat16* src = (arr ? g_qkl : g_qkh)
            + (size_t)(b * S + q0 + r) * 2048 + h * 64 + c * 8;
        cp16(sb + (uint32_t)(arr * 9216 + r * 72 + c * 8) * 2, src);
    }
    attn_issue_kv(b, h, 0, sb, 0, tid);
    cp_commit();

    float Oc[8][4] = {};
    float z0 = 0.f, z1 = 0.f, zm0 = 0.f, zm1 = 0.f;

    const uint32_t qrow_off = (uint32_t)((wid * 16 + (lane & 15)) * 72 + (lane >> 4) * 8);
    const float* mrow = Min + ((size_t)(b * S + q0 + wid * 16 + (lane >> 2))) * S
                        + (lane & 3) * 2;

    const int niter = S / 64;
    for (int it = 0; it < niter; ++it) {
        const int p = it & 1;
        if (it + 1 < niter) {
            attn_issue_kv(b, h, it + 1, sb, p ^ 1, tid);
            cp_commit();
            cp_wait1();
        } else {
            cp_wait0();
        }

        // mask -> 2 bit-masks (M is exactly 0/1; frees ~30 regs vs floats)
        uint32_t mbits0 = 0u, mbits1 = 0u;
        {
            const float* mb = mrow + it * 64;
            #pragma unroll
            for (int j = 0; j < 8; j++) {
                float2 a = *(const float2*)(mb + j * 8);
                float2 c = *(const float2*)(mb + (size_t)8 * S + j * 8);
                if (a.x != 0.f) mbits0 |= 1u << (2 * j);
                if (a.y != 0.f) mbits0 |= 1u << (2 * j + 1);
                if (c.x != 0.f) mbits1 |= 1u << (2 * j);
                if (c.y != 0.f) mbits1 |= 1u << (2 * j + 1);
            }
        }

        __syncthreads();   // KV buffer p ready

        const uint32_t kvb = 18432u + (uint32_t)p * 18432u;

        // cache Q frags (hi+lo) in registers
        uint32_t qh[4][4], ql[4][4];
        #pragma unroll
        for (int kk = 0; kk < 4; kk++) {
            ldsm_x4(qh[kk], sb + (qrow_off + (uint32_t)(kk * 16)) * 2);
            ldsm_x4(ql[kk], sb + (9216u + qrow_off + (uint32_t)(kk * 16)) * 2);
        }

        // scores: 3-term split, K frags loaded once each
        float sc[8][4] = {};
        #pragma unroll
        for (int jp = 0; jp < 4; jp++) {
            const uint32_t krow = (uint32_t)((jp * 16 + (lane & 15)) * 72 + (lane >> 4) * 8);
            #pragma unroll
            for (int kk = 0; kk < 4; kk++) {
                uint32_t kh[4];
                ldsm_x4(kh, sb + (kvb + krow + (uint32_t)(kk * 16)) * 2);
                mma16816(sc[jp * 2 + 0], qh[kk], kh[0], kh[2]);
                mma16816(sc[jp * 2 + 1], qh[kk], kh[1], kh[3]);
                mma16816(sc[jp * 2 + 0], ql[kk], kh[0], kh[2]);
                mma16816(sc[jp * 2 + 1], ql[kk], kh[1], kh[3]);
                uint32_t kl[4];
                ldsm_x4(kl, sb + (kvb + 4608u + krow + (uint32_t)(kk * 16)) * 2);
                mma16816(sc[jp * 2 + 0], qh[kk], kl[0], kl[2]);
                mma16816(sc[jp * 2 + 1], qh[kk], kl[1], kl[3]);
            }
        }

        // exp + bit-mask + sums + repack P (split hi/lo) into a-frags
        uint32_t pah[4][4], pal[4][4];
        #pragma unroll
        for (int j = 0; j < 8; j++) {
            float e0 = __expf(sc[j][0]);
            float e1 = __expf(sc[j][1]);
            float e2 = __expf(sc[j][2]);
            float e3 = __expf(sc[j][3]);
            z0 += e0 + e1; z1 += e2 + e3;
            float em0 = (mbits0 & (1u << (2 * j)))     ? e0 : 0.0f;
            float em1 = (mbits0 & (1u << (2 * j + 1))) ? e1 : 0.0f;
            float em2 = (mbits1 & (1u << (2 * j)))     ? e2 : 0.0f;
            float em3 = (mbits1 & (1u << (2 * j + 1))) ? e3 : 0.0f;
            zm0 += em0 + em1; zm1 += em2 + em3;
            float h0 = __bfloat162float(__float2bfloat16(em0));
            float h1 = __bfloat162float(__float2bfloat16(em1));
            float h2 = __bfloat162float(__float2bfloat16(em2));
            float h3 = __bfloat162float(__float2bfloat16(em3));
            pah[j >> 1][(j & 1) * 2 + 0] = bf2pack(em0, em1);
            pah[j >> 1][(j & 1) * 2 + 1] = bf2pack(em2, em3);
            pal[j >> 1][(j & 1) * 2 + 0] = bf2pack(em0 - h0, em1 - h1);
            pal[j >> 1][(j & 1) * 2 + 1] = bf2pack(em2 - h2, em3 - h3);
        }

        // PV: 3-term split, V frags loaded once each
        #pragma unroll
        for (int j2 = 0; j2 < 4; j2++) {
            const uint32_t vrow = (uint32_t)((j2 * 16 + ((lane >> 3) & 1) * 8 + (lane & 7)) * 72
                                             + (lane >> 4) * 8);
            #pragma unroll
            for (int ndp = 0; ndp < 4; ndp++) {
                uint32_t vh[4];
                ldsm_x4_t(vh, sb + (kvb + 9216u + vrow + (uint32_t)(ndp * 16)) * 2);
                mma16816(Oc[ndp * 2 + 0], pah[j2], vh[0], vh[1]);
                mma16816(Oc[ndp * 2 + 1], pah[j2], vh[2], vh[3]);
                mma16816(Oc[ndp * 2 + 0], pal[j2], vh[0], vh[1]);
                mma16816(Oc[ndp * 2 + 1], pal[j2], vh[2], vh[3]);
                uint32_t vl[4];
                ldsm_x4_t(vl, sb + (kvb + 13824u + vrow + (uint32_t)(ndp * 16)) * 2);
                mma16816(Oc[ndp * 2 + 0], pah[j2], vl[0], vl[1]);
                mma16816(Oc[ndp * 2 + 1], pah[j2], vl[2], vl[3]);
            }
        }
        __syncthreads();   // all reads of buffer p done before next issue overwrites it
    }

    // quad reduce (lanes sharing lane>>2 hold the same rows)
    #pragma unroll
    for (int off = 1; off < 4; off <<= 1) {
        z0  += __shfl_xor_sync(0xffffffffu, z0, off);
        z1  += __shfl_xor_sync(0xffffffffu, z1, off);
        zm0 += __shfl_xor_sync(0xffffffffu, zm0, off);
        zm1 += __shfl_xor_sync(0xffffffffu, zm1, off);
    }
    const float inv0 = 1.0f / (zm0 + EPSV * z0);
    const float inv1 = 1.0f / (zm1 + EPSV * z1);

    const int row = b * S + q0 + wid * 16 + (lane >> 2);
    #pragma unroll
    for (int nd = 0; nd < 8; nd++) {
        const int col = h * 64 + nd * 8 + (lane & 3) * 2;
        split_store(g_ath, g_atl, (size_t)row * D + col,
                    Oc[nd][0] * inv0, Oc[nd][1] * inv0);
        split_store(g_ath, g_atl, (size_t)(row + 8) * D + col,
                    Oc[nd][2] * inv1, Oc[nd][3] * inv1);
    }
}

// ---------------------------------------------------------------------------
extern "C" void kernel_launch(void* const* d_in, const int* in_sizes, int n_in,
                              void* d_out, int out_size) {
    const float* x         = (const float*)d_in[0];  // [B,S,D]
    const float* Vin       = (const float*)d_in[1];  // [B,S,H,HD]
    const float* Min       = (const float*)d_in[2];  // [B,S,S]
    const float* in_proj_w = (const float*)d_in[3];  // [3D,D]
    const float* in_proj_b = (const float*)d_in[4];  // [3D]
    const float* out_w     = (const float*)d_in[5];  // [D,D]
    const float* out_b     = (const float*)d_in[6];  // [D]
    float* out             = (float*)d_out;          // [B,S,D]

    __nv_bfloat16 *xh, *xl, *w1h, *w1l, *w3h, *w3l, *qkh, *qkl, *ath, *atl;
    cudaGetSymbolAddress((void**)&xh,  g_xh);
    cudaGetSymbolAddress((void**)&xl,  g_xl);
    cudaGetSymbolAddress((void**)&w1h, g_w1h);
    cudaGetSymbolAddress((void**)&w1l, g_w1l);
    cudaGetSymbolAddress((void**)&w3h, g_w3h);
    cudaGetSymbolAddress((void**)&w3l, g_w3l);
    cudaGetSymbolAddress((void**)&qkh, g_qkh);
    cudaGetSymbolAddress((void**)&qkl, g_qkl);
    cudaGetSymbolAddress((void**)&ath, g_ath);
    cudaGetSymbolAddress((void**)&atl, g_atl);

    cudaFuncSetAttribute(mma_gemm, cudaFuncAttributeMaxDynamicSharedMemorySize, GEMM_SMEM);
    cudaFuncSetAttribute(attn_mma, cudaFuncAttributeMaxDynamicSharedMemorySize, ATTN_SMEM);

    const int Mtot = Bsz * S;  // 4096

    // fused conversions (bf16 hi/lo splits for x, w1, w3, V)
    conv_all<<<(CNT + 255) / 256, 256>>>(x, in_proj_w, out_w, Vin);

    // Stage 1: [Q|K] = x @ in_proj_w[0:2D]^T + b -> bf16 hi/lo, Q scaled 1/8
    mma_gemm<<<dim3((2 * D) / 128, Mtot / 128), 256, GEMM_SMEM>>>(
        xh, xl, w1h, w1l, in_proj_b, nullptr, qkh, qkl, D, 2 * D, 1);

    // Stage 2: masked-renormalized attention -> bf16 hi/lo [4096][1024]
    attn_mma<<<dim3(S / 128, H, Bsz), 256, ATTN_SMEM>>>(Min);

    // Stage 3: out = attn @ out_w^T + out_b  (fp32)
    mma_gemm<<<dim3(D / 128, Mtot / 128), 256, GEMM_SMEM>>>(
        ath, atl, w3h, w3l, out_b, out, nullptr, nullptr, D, D, 0);
}

// round 9
// speedup vs baseline: 1.4923x; 1.3167x over previous
#include <cuda_runtime.h>
#include <cuda_bf16.h>
#include <cuda_fp16.h>
#include <cstdint>

#define Bsz 2
#define S   2048
#define D   1024
#define H   16
#define HD  64

// ---------------- scratch (__device__ globals; alloc-free rule) -------------
__device__ __nv_bfloat16 g_xh[(size_t)Bsz * S * D];
__device__ __nv_bfloat16 g_xl[(size_t)Bsz * S * D];
__device__ __nv_bfloat16 g_w1h[(size_t)2 * D * D];
__device__ __nv_bfloat16 g_w1l[(size_t)2 * D * D];
__device__ __nv_bfloat16 g_w3h[(size_t)D * D];
__device__ __nv_bfloat16 g_w3l[(size_t)D * D];
__device__ __half g_qkh[(size_t)Bsz * S * 2 * D];   // Q: fp16 hi (pre-scaled 0.125*log2e) | K: fp16 single
__device__ __half g_qkl[(size_t)Bsz * S * 2 * D];   // Q: fp16 lo (K region unused)
__device__ __half g_vh[(size_t)Bsz * S * D];        // V fp16 single
__device__ uint32_t g_mb[262144];                   // packed mask bits
__device__ __nv_bfloat16 g_ath[(size_t)Bsz * S * D];  // attention out hi (bf16 split for stage3)
__device__ __nv_bfloat16 g_atl[(size_t)Bsz * S * D];

// ---------------- helpers (all plain sm_80+ PTX; no 'a' features) -----------
__device__ __forceinline__ uint32_t smem_u32(const void* p) {
    uint32_t a;
    asm("{ .reg .u64 t; cvta.to.shared.u64 t, %1; cvt.u32.u64 %0, t; }" : "=r"(a) : "l"(p));
    return a;
}
__device__ __forceinline__ void cp16(uint32_t dst, const void* src) {
    asm volatile("cp.async.cg.shared.global [%0], [%1], 16;" :: "r"(dst), "l"(src));
}
__device__ __forceinline__ void cp_commit() {
    asm volatile("cp.async.commit_group;" ::: "memory");
}
__device__ __forceinline__ void cp_wait0() {
    asm volatile("cp.async.wait_group 0;" ::: "memory");
}
__device__ __forceinline__ void cp_wait1() {
    asm volatile("cp.async.wait_group 1;" ::: "memory");
}
__device__ __forceinline__ void ldsm_x4(uint32_t (&r)[4], uint32_t addr) {
    asm volatile("ldmatrix.sync.aligned.m8n8.x4.shared.b16 {%0,%1,%2,%3}, [%4];"
                 : "=r"(r[0]), "=r"(r[1]), "=r"(r[2]), "=r"(r[3]) : "r"(addr));
}
__device__ __forceinline__ void ldsm_x4_t(uint32_t (&r)[4], uint32_t addr) {
    asm volatile("ldmatrix.sync.aligned.m8n8.x4.trans.shared.b16 {%0,%1,%2,%3}, [%4];"
                 : "=r"(r[0]), "=r"(r[1]), "=r"(r[2]), "=r"(r[3]) : "r"(addr));
}
__device__ __forceinline__ void mma16816(float (&c)[4], const uint32_t (&a)[4],
                                         uint32_t b0, uint32_t b1) {
    asm volatile(
        "mma.sync.aligned.m16n8k16.row.col.f32.bf16.bf16.f32 "
        "{%0,%1,%2,%3}, {%4,%5,%6,%7}, {%8,%9}, {%0,%1,%2,%3};"
        : "+f"(c[0]), "+f"(c[1]), "+f"(c[2]), "+f"(c[3])
        : "r"(a[0]), "r"(a[1]), "r"(a[2]), "r"(a[3]), "r"(b0), "r"(b1));
}
__device__ __forceinline__ void mma16816h(float (&c)[4], const uint32_t (&a)[4],
                                          uint32_t b0, uint32_t b1) {
    asm volatile(
        "mma.sync.aligned.m16n8k16.row.col.f32.f16.f16.f32 "
        "{%0,%1,%2,%3}, {%4,%5,%6,%7}, {%8,%9}, {%0,%1,%2,%3};"
        : "+f"(c[0]), "+f"(c[1]), "+f"(c[2]), "+f"(c[3])
        : "r"(a[0]), "r"(a[1]), "r"(a[2]), "r"(a[3]), "r"(b0), "r"(b1));
}
__device__ __forceinline__ uint32_t h2pack(float lo, float hi) {
    uint32_t r;
    asm("cvt.rn.f16x2.f32 %0, %1, %2;" : "=r"(r) : "f"(hi), "f"(lo));
    return r;
}
__device__ __forceinline__ float ex2(float x) {
    float r;
    asm("ex2.approx.f32 %0, %1;" : "=f"(r) : "f"(x));
    return r;
}
__device__ __forceinline__ void split_store(__nv_bfloat16* Oh, __nv_bfloat16* Ol,
                                            size_t idx, float v0, float v1) {
    __nv_bfloat16 h0 = __float2bfloat16(v0), h1 = __float2bfloat16(v1);
    __nv_bfloat162 hp; hp.x = h0; hp.y = h1;
    __nv_bfloat162 lp;
    lp.x = __float2bfloat16(v0 - __bfloat162float(h0));
    lp.y = __float2bfloat16(v1 - __bfloat162float(h1));
    *(__nv_bfloat162*)(Oh + idx) = hp;
    *(__nv_bfloat162*)(Ol + idx) = lp;
}
__device__ __forceinline__ void split_store_h(__half* Oh, __half* Ol,
                                              size_t idx, float v0, float v1) {
    __half h0 = __float2half_rn(v0), h1 = __float2half_rn(v1);
    __half2 hp; hp.x = h0; hp.y = h1;
    __half2 lp;
    lp.x = __float2half_rn(v0 - __half2float(h0));
    lp.y = __float2half_rn(v1 - __half2float(h1));
    *(__half2*)(Oh + idx) = hp;
    *(__half2*)(Ol + idx) = lp;
}

// ---------------------------------------------------------------------------
// Fused conversions: x/w1/w3 -> bf16 hi/lo; V -> fp16 single.
// ---------------------------------------------------------------------------
#define CN1 1048576   // x  float4s
#define CN2 524288    // w1
#define CN3 262144    // w3
#define CN4 1048576   // V
#define CNT (CN1 + CN2 + CN3 + CN4)

__global__ __launch_bounds__(256)
void conv_all(const float* __restrict__ x, const float* __restrict__ w1,
              const float* __restrict__ w3, const float* __restrict__ Vin) {
    int i = blockIdx.x * 256 + threadIdx.x;
    if (i >= CNT) return;
    int j = i;
    if (j >= CN1 + CN2 + CN3) {   // V -> fp16 single
        j -= CN1 + CN2 + CN3;
        float4 v = *(const float4*)(Vin + (size_t)j * 4);
        __half2 a; a.x = __float2half_rn(v.x); a.y = __float2half_rn(v.y);
        __half2 b; b.x = __float2half_rn(v.z); b.y = __float2half_rn(v.w);
        __half2* p = (__half2*)(g_vh + (size_t)j * 4);
        p[0] = a; p[1] = b;
        return;
    }
    const float* src;
    __nv_bfloat16 *hi, *lo;
    if (j < CN1) { src = x; hi = g_xh; lo = g_xl; }
    else if ((j -= CN1) < CN2) { src = w1; hi = g_w1h; lo = g_w1l; }
    else { j -= CN2; src = w3; hi = g_w3h; lo = g_w3l; }
    float4 v = *(const float4*)(src + (size_t)j * 4);
    split_store(hi, lo, (size_t)j * 4, v.x, v.y);
    split_store(hi, lo, (size_t)j * 4 + 2, v.z, v.w);
}

// ---------------------------------------------------------------------------
// Mask bit-pack pre-pass. Word layout matches attention's per-thread frags:
// idx = (((b*128 + qg)*8 + r8)*32 + it)*4 + lg
// bits [2j], [2j+1]   : M[b][qg*16+r8][it*64 + lg*2 + j*8 + {0,1}]
// bits [16+2j],[17+2j]: same cols, row +8
// ---------------------------------------------------------------------------
__global__ __launch_bounds__(256)
void mask_pre(const float* __restrict__ Min) {
    int idx = blockIdx.x * 256 + threadIdx.x;   // 262144 total
    int lg = idx & 3, it = (idx >> 2) & 31, r8 = (idx >> 7) & 7;
    int qg = (idx >> 10) & 127, b = idx >> 17;
    const float* base = Min + ((size_t)b * S + qg * 16 + r8) * S + it * 64 + lg * 2;
    uint32_t w = 0;
    #pragma unroll
    for (int j = 0; j < 8; j++) {
        float2 a = *(const float2*)(base + j * 8);
        float2 c = *(const float2*)(base + (size_t)8 * S + j * 8);
        if (a.x != 0.f) w |= 1u << (2 * j);
        if (a.y != 0.f) w |= 1u << (2 * j + 1);
        if (c.x != 0.f) w |= 1u << (16 + 2 * j);
        if (c.y != 0.f) w |= 1u << (17 + 2 * j);
    }
    g_mb[idx] = w;
}

// ---------------------------------------------------------------------------
// mma.sync bf16x3 GEMM (projections): C = (Ah+Al)(Bh+Bl)^T + bias
// mode 0: fp32 out. mode 1: Q cols -> fp16 split scaled 0.125*log2e; K -> fp16.
// ---------------------------------------------------------------------------
#define GEMM_SMEM (2 * 20480 * 2)
#define QSC 0.180336880f   // 0.125 * log2(e)

__device__ __forceinline__ void gemm_issue(
    const __nv_bfloat16* Ah, const __nv_bfloat16* Al,
    const __nv_bfloat16* Bh, const __nv_bfloat16* Bl,
    int K, int row0, int col0, int chunk, uint32_t dstbase, int tid) {
    #pragma unroll
    for (int j = 0; j < 8; j++) {
        int linear = tid + j * 256;
        int arr = linear >> 9, rem = linear & 511;
        int r = rem >> 2, c = rem & 3;
        const __nv_bfloat16* src = (arr == 0) ? Ah : (arr == 1) ? Al : (arr == 2) ? Bh : Bl;
        int grow = ((arr < 2) ? row0 : col0) + r;
        cp16(dstbase + (uint32_t)(arr * 5120 + r * 40 + c * 8) * 2,
             src + (size_t)grow * K + chunk * 32 + c * 8);
    }
}

__global__ __launch_bounds__(256, 2)
void mma_gemm(const __nv_bfloat16* __restrict__ Ah, const __nv_bfloat16* __restrict__ Al,
              const __nv_bfloat16* __restrict__ Bh, const __nv_bfloat16* __restrict__ Bl,
              const float* __restrict__ bias, float* __restrict__ Cf,
              __half* __restrict__ Oh, __half* __restrict__ Ol,
              int K, int N, int mode) {
    extern __shared__ __nv_bfloat16 smem[];
    const int tid = threadIdx.x;
    const int wid = tid >> 5, lane = tid & 31;
    const int wr = wid >> 2, wc = wid & 3;
    const int row0 = blockIdx.y * 128, col0 = blockIdx.x * 128;
    const uint32_t sb = smem_u32(smem);

    float acc[4][4][4] = {};

    gemm_issue(Ah, Al, Bh, Bl, K, row0, col0, 0, sb, tid);
    cp_commit();

    const int nch = K / 32;
    for (int ch = 0; ch < nch; ++ch) {
        const int p = ch & 1;
        if (ch + 1 < nch) {
            gemm_issue(Ah, Al, Bh, Bl, K, row0, col0, ch + 1, sb + (p ^ 1) * 40960, tid);
            cp_commit();
            cp_wait1();
        } else {
            cp_wait0();
        }
        __syncthreads();

        const uint32_t bufb = sb + p * 40960;
        #pragma unroll
        for (int t = 0; t < 3; t++) {
            const uint32_t aoff = (t == 2) ? 5120u : 0u;
            const uint32_t boff = (t == 1) ? 15360u : 10240u;
            #pragma unroll
            for (int kk = 0; kk < 2; kk++) {
                uint32_t a[4][4];
                #pragma unroll
                for (int i = 0; i < 4; i++)
                    ldsm_x4(a[i], bufb + (aoff + (uint32_t)((wr * 64 + i * 16 + (lane & 15)) * 40
                                                  + kk * 16 + (lane >> 4) * 8)) * 2);
                #pragma unroll
                for (int jp = 0; jp < 2; jp++) {
                    uint32_t r4[4];
                    ldsm_x4(r4, bufb + (boff + (uint32_t)((wc * 32 + jp * 16 + (lane & 15)) * 40
                                                  + kk * 16 + (lane >> 4) * 8)) * 2);
                    #pragma unroll
                    for (int i = 0; i < 4; i++) {
                        mma16816(acc[i][jp * 2 + 0], a[i], r4[0], r4[2]);
                        mma16816(acc[i][jp * 2 + 1], a[i], r4[1], r4[3]);
                    }
                }
            }
        }
        __syncthreads();
    }

    const bool isQ = (mode == 1 && col0 < D);
    #pragma unroll
    for (int j = 0; j < 4; j++) {
        const int col = col0 + wc * 32 + j * 8 + (lane & 3) * 2;
        const float b0 = bias[col], b1 = bias[col + 1];
        #pragma unroll
        for (int i = 0; i < 4; i++) {
            const int row = row0 + wr * 64 + i * 16 + (lane >> 2);
            float v0 = acc[i][j][0] + b0, v1 = acc[i][j][1] + b1;
            float w0 = acc[i][j][2] + b0, w1 = acc[i][j][3] + b1;
            if (mode == 0) {
                *(float2*)(Cf + (size_t)row * N + col) = make_float2(v0, v1);
                *(float2*)(Cf + (size_t)(row + 8) * N + col) = make_float2(w0, w1);
            } else if (isQ) {
                split_store_h(Oh, Ol, (size_t)row * N + col, v0 * QSC, v1 * QSC);
                split_store_h(Oh, Ol, (size_t)(row + 8) * N + col, w0 * QSC, w1 * QSC);
            } else {   // K: single fp16
                __half2 a; a.x = __float2half_rn(v0); a.y = __float2half_rn(v1);
                __half2 b; b.x = __float2half_rn(w0); b.y = __float2half_rn(w1);
                *(__half2*)(Oh + (size_t)row * N + col) = a;
                *(__half2*)(Oh + (size_t)(row + 8) * N + col) = b;
            }
        }
    }
}

// ---------------------------------------------------------------------------
// Attention (fp16 mma). Per CTA: 128 q rows; 8 warps x 16q x 64k per iter.
// Scores = (Qh+Ql)·K (K single fp16, Q pre-scaled 0.125*log2e; e = ex2(s)).
// PV = P·V (P,V single fp16). Mask from packed bits. out = O / Zm.
// smem halves: Qh@0, Ql@9216, KV @18432, 2 buffers stride 9216 (K@0, V@4608).
// ---------------------------------------------------------------------------
#define ATTN_SMEM ((18432 + 2 * 9216) * 2)

__device__ __forceinline__ void attn_issue_kv(int b, int h, int it, uint32_t sb,
                                              int p, int tid) {
    const int k0 = it * 64;
    #pragma unroll
    for (int j = 0; j < 4; j++) {
        int linear = tid + j * 256;
        int arr = linear >> 9, rem = linear & 511;
        int r = rem >> 3, c = rem & 7;
        const __half* src = arr
            ? g_vh + (size_t)(b * S + k0 + r) * 1024 + h * 64 + c * 8
            : g_qkh + (size_t)(b * S + k0 + r) * 2048 + D + h * 64 + c * 8;
        cp16(sb + (uint32_t)(18432 + p * 9216 + arr * 4608 + r * 72 + c * 8) * 2, src);
    }
}

__global__ __launch_bounds__(256, 2)
void attn_mma() {
    extern __shared__ __half smh[];
    const int tid = threadIdx.x;
    const int wid = tid >> 5, lane = tid & 31;
    const int b = blockIdx.z, h = blockIdx.y;
    const int q0 = blockIdx.x * 128;
    const uint32_t sb = smem_u32(smh);

    // Q hi/lo -> smem (same commit group as iter-0 K/V)
    #pragma unroll
    for (int j = 0; j < 8; j++) {
        int linear = tid + j * 256;
        int arr = linear >> 10, rem = linear & 1023;
        int r = rem >> 3, c = rem & 7;
        const __half* src = (arr ? g_qkl : g_qkh)
            + (size_t)(b * S + q0 + r) * 2048 + h * 64 + c * 8;
        cp16(sb + (uint32_t)(arr * 9216 + r * 72 + c * 8) * 2, src);
    }
    attn_issue_kv(b, h, 0, sb, 0, tid);
    cp_commit();

    float Oc[8][4] = {};
    float zm0 = 0.f, zm1 = 0.f;

    const uint32_t qrow_off = (uint32_t)((wid * 16 + (lane & 15)) * 72 + (lane >> 4) * 8);
    const uint32_t* mp = g_mb
        + (size_t)((b * 128 + blockIdx.x * 8 + wid) * 8 + (lane >> 2)) * 128 + (lane & 3);

    const int niter = S / 64;
    for (int it = 0; it < niter; ++it) {
        const int p = it & 1;
        if (it + 1 < niter) {
            attn_issue_kv(b, h, it + 1, sb, p ^ 1, tid);
            cp_commit();
            cp_wait1();
        } else {
            cp_wait0();
        }

        const uint32_t mw = mp[it * 4];   // packed mask bits for this tile

        __syncthreads();   // KV buffer p ready

        const uint32_t kvb = 18432u + (uint32_t)p * 9216u;

        // cache Q frags (hi+lo) in registers
        uint32_t qh[4][4], ql[4][4];
        #pragma unroll
        for (int kk = 0; kk < 4; kk++) {
            ldsm_x4(qh[kk], sb + (qrow_off + (uint32_t)(kk * 16)) * 2);
            ldsm_x4(ql[kk], sb + (9216u + qrow_off + (uint32_t)(kk * 16)) * 2);
        }

        // scores: 2-term (Qh + Ql) x K-single
        float sc[8][4] = {};
        #pragma unroll
        for (int jp = 0; jp < 4; jp++) {
            const uint32_t krow = (uint32_t)((jp * 16 + (lane & 15)) * 72 + (lane >> 4) * 8);
            #pragma unroll
            for (int kk = 0; kk < 4; kk++) {
                uint32_t kh[4];
                ldsm_x4(kh, sb + (kvb + krow + (uint32_t)(kk * 16)) * 2);
                mma16816h(sc[jp * 2 + 0], qh[kk], kh[0], kh[2]);
                mma16816h(sc[jp * 2 + 1], qh[kk], kh[1], kh[3]);
                mma16816h(sc[jp * 2 + 0], ql[kk], kh[0], kh[2]);
                mma16816h(sc[jp * 2 + 1], ql[kk], kh[1], kh[3]);
            }
        }

        // ex2 + bit-mask + Zm + repack P (single fp16) into a-frags
        uint32_t pa[4][4];
        #pragma unroll
        for (int j = 0; j < 8; j++) {
            float e0 = ex2(sc[j][0]);
            float e1 = ex2(sc[j][1]);
            float e2 = ex2(sc[j][2]);
            float e3 = ex2(sc[j][3]);
            float em0 = (mw & (1u << (2 * j)))      ? e0 : 0.0f;
            float em1 = (mw & (1u << (2 * j + 1)))  ? e1 : 0.0f;
            float em2 = (mw & (1u << (16 + 2 * j))) ? e2 : 0.0f;
            float em3 = (mw & (1u << (17 + 2 * j))) ? e3 : 0.0f;
            zm0 += em0 + em1; zm1 += em2 + em3;
            pa[j >> 1][(j & 1) * 2 + 0] = h2pack(em0, em1);
            pa[j >> 1][(j & 1) * 2 + 1] = h2pack(em2, em3);
        }

        // PV: single term, V frags loaded once each
        #pragma unroll
        for (int j2 = 0; j2 < 4; j2++) {
            const uint32_t vrow = (uint32_t)((j2 * 16 + ((lane >> 3) & 1) * 8 + (lane & 7)) * 72
                                             + (lane >> 4) * 8);
            #pragma unroll
            for (int ndp = 0; ndp < 4; ndp++) {
                uint32_t vh[4];
                ldsm_x4_t(vh, sb + (kvb + 4608u + vrow + (uint32_t)(ndp * 16)) * 2);
                mma16816h(Oc[ndp * 2 + 0], pa[j2], vh[0], vh[1]);
                mma16816h(Oc[ndp * 2 + 1], pa[j2], vh[2], vh[3]);
            }
        }
        __syncthreads();   // reads of buffer p done before next issue overwrites it
    }

    // quad reduce Zm (lanes sharing lane>>2 hold the same rows)
    #pragma unroll
    for (int off = 1; off < 4; off <<= 1) {
        zm0 += __shfl_xor_sync(0xffffffffu, zm0, off);
        zm1 += __shfl_xor_sync(0xffffffffu, zm1, off);
    }
    const float inv0 = 1.0f / zm0;
    const float inv1 = 1.0f / zm1;

    const int row = b * S + q0 + wid * 16 + (lane >> 2);
    #pragma unroll
    for (int nd = 0; nd < 8; nd++) {
        const int col = h * 64 + nd * 8 + (lane & 3) * 2;
        split_store(g_ath, g_atl, (size_t)row * D + col,
                    Oc[nd][0] * inv0, Oc[nd][1] * inv0);
        split_store(g_ath, g_atl, (size_t)(row + 8) * D + col,
                    Oc[nd][2] * inv1, Oc[nd][3] * inv1);
    }
}

// ---------------------------------------------------------------------------
extern "C" void kernel_launch(void* const* d_in, const int* in_sizes, int n_in,
                              void* d_out, int out_size) {
    const float* x         = (const float*)d_in[0];  // [B,S,D]
    const float* Vin       = (const float*)d_in[1];  // [B,S,H,HD]
    const float* Min       = (const float*)d_in[2];  // [B,S,S]
    const float* in_proj_w = (const float*)d_in[3];  // [3D,D]
    const float* in_proj_b = (const float*)d_in[4];  // [3D]
    const float* out_w     = (const float*)d_in[5];  // [D,D]
    const float* out_b     = (const float*)d_in[6];  // [D]
    float* out             = (float*)d_out;          // [B,S,D]

    __nv_bfloat16 *xh, *xl, *w1h, *w1l, *w3h, *w3l, *ath, *atl;
    __half *qkh, *qkl;
    cudaGetSymbolAddress((void**)&xh,  g_xh);
    cudaGetSymbolAddress((void**)&xl,  g_xl);
    cudaGetSymbolAddress((void**)&w1h, g_w1h);
    cudaGetSymbolAddress((void**)&w1l, g_w1l);
    cudaGetSymbolAddress((void**)&w3h, g_w3h);
    cudaGetSymbolAddress((void**)&w3l, g_w3l);
    cudaGetSymbolAddress((void**)&qkh, g_qkh);
    cudaGetSymbolAddress((void**)&qkl, g_qkl);
    cudaGetSymbolAddress((void**)&ath, g_ath);
    cudaGetSymbolAddress((void**)&atl, g_atl);

    cudaFuncSetAttribute(mma_gemm, cudaFuncAttributeMaxDynamicSharedMemorySize, GEMM_SMEM);
    cudaFuncSetAttribute(attn_mma, cudaFuncAttributeMaxDynamicSharedMemorySize, ATTN_SMEM);

    const int Mtot = Bsz * S;  // 4096

    // conversions + mask bit-pack
    conv_all<<<(CNT + 255) / 256, 256>>>(x, in_proj_w, out_w, Vin);
    mask_pre<<<262144 / 256, 256>>>(Min);

    // Stage 1: [Q|K] = x @ in_proj_w[0:2D]^T + b -> fp16 (Q split+scaled, K single)
    mma_gemm<<<dim3((2 * D) / 128, Mtot / 128), 256, GEMM_SMEM>>>(
        xh, xl, w1h, w1l, in_proj_b, nullptr, qkh, qkl, D, 2 * D, 1);

    // Stage 2: masked-renormalized attention -> bf16 hi/lo [4096][1024]
    attn_mma<<<dim3(S / 128, H, Bsz), 256, ATTN_SMEM>>>();

    // Stage 3: out = attn @ out_w^T + out_b  (fp32)
    mma_gemm<<<dim3(D / 128, Mtot / 128), 256, GEMM_SMEM>>>(
        ath, atl, w3h, w3l, out_b, out, nullptr, nullptr, D, D, 0);
}

// round 10
// speedup vs baseline: 2.1604x; 1.4477x over previous
#include <cuda_runtime.h>
#include <cuda_fp16.h>
#include <cstdint>

#define Bsz 2
#define S   2048
#define D   1024
#define H   16
#define HD  64

// ---------------- scratch (__device__ globals; alloc-free rule) -------------
__device__ __half g_xh[(size_t)Bsz * S * D];        // x fp16 hi
__device__ __half g_xl[(size_t)Bsz * S * D];        // x fp16 lo
__device__ __half g_w1[(size_t)2 * D * D];          // in_proj_w[0:2D] fp16 single
__device__ __half g_w3[(size_t)D * D];              // out_w fp16 single
__device__ __half g_qk[(size_t)Bsz * S * 2 * D];    // Q (scaled 0.125*log2e) | K, fp16 single
__device__ __half g_vh[(size_t)Bsz * S * D];        // V fp16 single
__device__ uint32_t g_mb[262144];                   // packed mask bits
__device__ __half g_ath[(size_t)Bsz * S * D];       // attention out fp16 hi
__device__ __half g_atl[(size_t)Bsz * S * D];       // attention out fp16 lo

// ---------------- helpers (all plain sm_80+ PTX; no 'a' features) -----------
__device__ __forceinline__ uint32_t smem_u32(const void* p) {
    uint32_t a;
    asm("{ .reg .u64 t; cvta.to.shared.u64 t, %1; cvt.u32.u64 %0, t; }" : "=r"(a) : "l"(p));
    return a;
}
__device__ __forceinline__ void cp16(uint32_t dst, const void* src) {
    asm volatile("cp.async.cg.shared.global [%0], [%1], 16;" :: "r"(dst), "l"(src));
}
__device__ __forceinline__ void cp_commit() {
    asm volatile("cp.async.commit_group;" ::: "memory");
}
__device__ __forceinline__ void cp_wait0() {
    asm volatile("cp.async.wait_group 0;" ::: "memory");
}
__device__ __forceinline__ void cp_wait1() {
    asm volatile("cp.async.wait_group 1;" ::: "memory");
}
__device__ __forceinline__ void ldsm_x4(uint32_t (&r)[4], uint32_t addr) {
    asm volatile("ldmatrix.sync.aligned.m8n8.x4.shared.b16 {%0,%1,%2,%3}, [%4];"
                 : "=r"(r[0]), "=r"(r[1]), "=r"(r[2]), "=r"(r[3]) : "r"(addr));
}
__device__ __forceinline__ void ldsm_x4_t(uint32_t (&r)[4], uint32_t addr) {
    asm volatile("ldmatrix.sync.aligned.m8n8.x4.trans.shared.b16 {%0,%1,%2,%3}, [%4];"
                 : "=r"(r[0]), "=r"(r[1]), "=r"(r[2]), "=r"(r[3]) : "r"(addr));
}
__device__ __forceinline__ void mma16816h(float (&c)[4], const uint32_t (&a)[4],
                                          uint32_t b0, uint32_t b1) {
    asm volatile(
        "mma.sync.aligned.m16n8k16.row.col.f32.f16.f16.f32 "
        "{%0,%1,%2,%3}, {%4,%5,%6,%7}, {%8,%9}, {%0,%1,%2,%3};"
        : "+f"(c[0]), "+f"(c[1]), "+f"(c[2]), "+f"(c[3])
        : "r"(a[0]), "r"(a[1]), "r"(a[2]), "r"(a[3]), "r"(b0), "r"(b1));
}
__device__ __forceinline__ uint32_t h2pack(float lo, float hi) {
    uint32_t r;
    asm("cvt.rn.f16x2.f32 %0, %1, %2;" : "=r"(r) : "f"(hi), "f"(lo));
    return r;
}
__device__ __forceinline__ float ex2(float x) {
    float r;
    asm("ex2.approx.f32 %0, %1;" : "=f"(r) : "f"(x));
    return r;
}
__device__ __forceinline__ void split_store_h(__half* Oh, __half* Ol,
                                              size_t idx, float v0, float v1) {
    __half h0 = __float2half_rn(v0), h1 = __float2half_rn(v1);
    __half2 hp; hp.x = h0; hp.y = h1;
    __half2 lp;
    lp.x = __float2half_rn(v0 - __half2float(h0));
    lp.y = __float2half_rn(v1 - __half2float(h1));
    *(__half2*)(Oh + idx) = hp;
    *(__half2*)(Ol + idx) = lp;
}
__device__ __forceinline__ void single_store_h(__half* Oh, size_t idx,
                                               float v0, float v1) {
    __half2 a; a.x = __float2half_rn(v0); a.y = __float2half_rn(v1);
    *(__half2*)(Oh + idx) = a;
}

// ---------------------------------------------------------------------------
// Fused conversions: x -> fp16 hi/lo; w1, w3, V -> fp16 single.
// ---------------------------------------------------------------------------
#define CN1 1048576   // x  float4s (split)
#define CN2 524288    // w1 (single)
#define CN3 262144    // w3 (single)
#define CN4 1048576   // V  (single)
#define CNT (CN1 + CN2 + CN3 + CN4)

__global__ __launch_bounds__(256)
void conv_all(const float* __restrict__ x, const float* __restrict__ w1,
              const float* __restrict__ w3, const float* __restrict__ Vin) {
    int i = blockIdx.x * 256 + threadIdx.x;
    if (i >= CNT) return;
    int j = i;
    if (j < CN1) {   // x split
        float4 v = *(const float4*)(x + (size_t)j * 4);
        split_store_h(g_xh, g_xl, (size_t)j * 4, v.x, v.y);
        split_store_h(g_xh, g_xl, (size_t)j * 4 + 2, v.z, v.w);
        return;
    }
    const float* src;
    __half* o;
    if ((j -= CN1) < CN2) { src = w1; o = g_w1; }
    else if ((j -= CN2) < CN3) { src = w3; o = g_w3; }
    else { j -= CN3; src = Vin; o = g_vh; }
    float4 v = *(const float4*)(src + (size_t)j * 4);
    single_store_h(o, (size_t)j * 4, v.x, v.y);
    single_store_h(o, (size_t)j * 4 + 2, v.z, v.w);
}

// ---------------------------------------------------------------------------
// Mask bit-pack pre-pass (layout matches attention's per-thread frags):
// idx = (((b*128 + qg)*8 + r8)*32 + it)*4 + lg
// ---------------------------------------------------------------------------
__global__ __launch_bounds__(256)
void mask_pre(const float* __restrict__ Min) {
    int idx = blockIdx.x * 256 + threadIdx.x;   // 262144 total
    int lg = idx & 3, it = (idx >> 2) & 31, r8 = (idx >> 7) & 7;
    int qg = (idx >> 10) & 127, b = idx >> 17;
    const float* base = Min + ((size_t)b * S + qg * 16 + r8) * S + it * 64 + lg * 2;
    uint32_t w = 0;
    #pragma unroll
    for (int j = 0; j < 8; j++) {
        float2 a = *(const float2*)(base + j * 8);
        float2 c = *(const float2*)(base + (size_t)8 * S + j * 8);
        if (a.x != 0.f) w |= 1u << (2 * j);
        if (a.y != 0.f) w |= 1u << (2 * j + 1);
        if (c.x != 0.f) w |= 1u << (16 + 2 * j);
        if (c.y != 0.f) w |= 1u << (17 + 2 * j);
    }
    g_mb[idx] = w;
}

// ---------------------------------------------------------------------------
// fp16 2-term GEMM: C = (Ah+Al)[M][K] * B[N][K]^T + bias
// 128x128 tile, BK=32, cp.async double-buffered, 8 warps (2x4).
// mode 0: fp32 out to Cf. mode 1: fp16 single out; Q cols scaled 0.125*log2e.
// smem/buf (halves): Ah@0, Al@5120, B@10240; stride 15360.
// ---------------------------------------------------------------------------
#define GEMM_SMEM (2 * 15360 * 2)
#define QSC 0.1803368801111204f   // 0.125 * log2(e)

__device__ __forceinline__ void gemm_issue(
    const __half* Ah, const __half* Al, const __half* Bw,
    int K, int row0, int col0, int chunk, uint32_t dstbase, int tid) {
    #pragma unroll
    for (int j = 0; j < 6; j++) {
        int linear = tid + j * 256;
        int arr = linear >> 9, rem = linear & 511;
        int r = rem >> 2, c = rem & 3;
        const __half* src = (arr == 0) ? Ah : (arr == 1) ? Al : Bw;
        int grow = ((arr < 2) ? row0 : col0) + r;
        cp16(dstbase + (uint32_t)(arr * 5120 + r * 40 + c * 8) * 2,
             src + (size_t)grow * K + chunk * 32 + c * 8);
    }
}

__global__ __launch_bounds__(256, 2)
void mma_gemm(const __half* __restrict__ Ah, const __half* __restrict__ Al,
              const __half* __restrict__ Bw,
              const float* __restrict__ bias, float* __restrict__ Cf,
              __half* __restrict__ Oh, int K, int N, int mode) {
    extern __shared__ __half smem[];
    const int tid = threadIdx.x;
    const int wid = tid >> 5, lane = tid & 31;
    const int wr = wid >> 2, wc = wid & 3;
    const int row0 = blockIdx.y * 128, col0 = blockIdx.x * 128;
    const uint32_t sb = smem_u32(smem);

    float acc[4][4][4] = {};

    gemm_issue(Ah, Al, Bw, K, row0, col0, 0, sb, tid);
    cp_commit();

    const int nch = K / 32;
    for (int ch = 0; ch < nch; ++ch) {
        const int p = ch & 1;
        if (ch + 1 < nch) {
            gemm_issue(Ah, Al, Bw, K, row0, col0, ch + 1, sb + (p ^ 1) * 30720, tid);
            cp_commit();
            cp_wait1();
        } else {
            cp_wait0();
        }
        __syncthreads();

        const uint32_t bufb = sb + p * 30720;
        #pragma unroll
        for (int kk = 0; kk < 2; kk++) {
            const uint32_t koffs = (uint32_t)(kk * 16 + (lane >> 4) * 8);
            uint32_t b0[4], b1[4];
            ldsm_x4(b0, bufb + (10240u + (uint32_t)((wc * 32 + (lane & 15)) * 40) + koffs) * 2);
            ldsm_x4(b1, bufb + (10240u + (uint32_t)((wc * 32 + 16 + (lane & 15)) * 40) + koffs) * 2);
            #pragma unroll
            for (int i = 0; i < 4; i++) {
                const uint32_t arow = (uint32_t)((wr * 64 + i * 16 + (lane & 15)) * 40) + koffs;
                uint32_t a4[4];
                ldsm_x4(a4, bufb + arow * 2);
                mma16816h(acc[i][0], a4, b0[0], b0[2]);
                mma16816h(acc[i][1], a4, b0[1], b0[3]);
                mma16816h(acc[i][2], a4, b1[0], b1[2]);
                mma16816h(acc[i][3], a4, b1[1], b1[3]);
                ldsm_x4(a4, bufb + (5120u + arow) * 2);
                mma16816h(acc[i][0], a4, b0[0], b0[2]);
                mma16816h(acc[i][1], a4, b0[1], b0[3]);
                mma16816h(acc[i][2], a4, b1[0], b1[2]);
                mma16816h(acc[i][3], a4, b1[1], b1[3]);
            }
        }
        __syncthreads();
    }

    const float qs = (mode == 1 && col0 < D) ? QSC : 1.0f;
    #pragma unroll
    for (int j = 0; j < 4; j++) {
        const int col = col0 + wc * 32 + j * 8 + (lane & 3) * 2;
        const float b0 = bias[col], b1 = bias[col + 1];
        #pragma unroll
        for (int i = 0; i < 4; i++) {
            const int row = row0 + wr * 64 + i * 16 + (lane >> 2);
            float v0 = (acc[i][j][0] + b0) * qs, v1 = (acc[i][j][1] + b1) * qs;
            float w0 = (acc[i][j][2] + b0) * qs, w1 = (acc[i][j][3] + b1) * qs;
            if (mode == 0) {
                *(float2*)(Cf + (size_t)row * N + col) = make_float2(v0, v1);
                *(float2*)(Cf + (size_t)(row + 8) * N + col) = make_float2(w0, w1);
            } else {
                single_store_h(Oh, (size_t)row * N + col, v0, v1);
                single_store_h(Oh, (size_t)(row + 8) * N + col, w0, w1);
            }
        }
    }
}

// ---------------------------------------------------------------------------
// Attention (fp16 mma, all-single). Per CTA: 128 q rows; 8 warps x 16q x 64k.
// Scores = Q·K (1 term; Q pre-scaled 0.125*log2e; e = ex2(s)); Q frags hoisted.
// PV = P·V single. Mask from packed bits. out = O / Zm (fp16 hi/lo out).
// smem halves: Q@0 (9216), 2 KV buffers @9216 stride 9216 (K@0, V@4608).
// ---------------------------------------------------------------------------
#define ATTN_SMEM ((9216 + 2 * 9216) * 2)

__device__ __forceinline__ void attn_issue_kv(int b, int h, int it, uint32_t sb,
                                              int p, int tid) {
    const int k0 = it * 64;
    #pragma unroll
    for (int j = 0; j < 4; j++) {
        int linear = tid + j * 256;
        int arr = linear >> 9, rem = linear & 511;
        int r = rem >> 3, c = rem & 7;
        const __half* src = arr
            ? g_vh + (size_t)(b * S + k0 + r) * 1024 + h * 64 + c * 8
            : g_qk + (size_t)(b * S + k0 + r) * 2048 + D + h * 64 + c * 8;
        cp16(sb + (uint32_t)(9216 + p * 9216 + arr * 4608 + r * 72 + c * 8) * 2, src);
    }
}

__global__ __launch_bounds__(256, 2)
void attn_mma() {
    extern __shared__ __half smh[];
    const int tid = threadIdx.x;
    const int wid = tid >> 5, lane = tid & 31;
    const int b = blockIdx.z, h = blockIdx.y;
    const int q0 = blockIdx.x * 128;
    const uint32_t sb = smem_u32(smh);

    // Q -> smem (same commit group as iter-0 K/V)
    #pragma unroll
    for (int j = 0; j < 4; j++) {
        int linear = tid + j * 256;
        int r = linear >> 3, c = linear & 7;
        cp16(sb + (uint32_t)(r * 72 + c * 8) * 2,
             g_qk + (size_t)(b * S + q0 + r) * 2048 + h * 64 + c * 8);
    }
    attn_issue_kv(b, h, 0, sb, 0, tid);
    cp_commit();

    float Oc[8][4] = {};
    float zm0 = 0.f, zm1 = 0.f;
    uint32_t qh[4][4];   // static Q frags, loaded once at it==0

    const uint32_t qrow_off = (uint32_t)((wid * 16 + (lane & 15)) * 72 + (lane >> 4) * 8);
    const uint32_t* mp = g_mb
        + (size_t)((b * 128 + blockIdx.x * 8 + wid) * 8 + (lane >> 2)) * 128 + (lane & 3);

    const int niter = S / 64;
    for (int it = 0; it < niter; ++it) {
        const int p = it & 1;
        if (it + 1 < niter) {
            attn_issue_kv(b, h, it + 1, sb, p ^ 1, tid);
            cp_commit();
            cp_wait1();
        } else {
            cp_wait0();
        }

        const uint32_t mw = mp[it * 4];

        __syncthreads();   // KV buffer p (and at it=0, Q) ready

        if (it == 0) {
            #pragma unroll
            for (int kk = 0; kk < 4; kk++)
                ldsm_x4(qh[kk], sb + (qrow_off + (uint32_t)(kk * 16)) * 2);
        }

        const uint32_t kvb = 9216u + (uint32_t)p * 9216u;

        // scores: single term Q x K
        float sc[8][4] = {};
        #pragma unroll
        for (int jp = 0; jp < 4; jp++) {
            const uint32_t krow = (uint32_t)((jp * 16 + (lane & 15)) * 72 + (lane >> 4) * 8);
            #pragma unroll
            for (int kk = 0; kk < 4; kk++) {
                uint32_t kh[4];
                ldsm_x4(kh, sb + (kvb + krow + (uint32_t)(kk * 16)) * 2);
                mma16816h(sc[jp * 2 + 0], qh[kk], kh[0], kh[2]);
                mma16816h(sc[jp * 2 + 1], qh[kk], kh[1], kh[3]);
            }
        }

        // ex2 + bit-mask + Zm + repack P (single fp16) into a-frags
        uint32_t pa[4][4];
        #pragma unroll
        for (int j = 0; j < 8; j++) {
            float e0 = ex2(sc[j][0]);
            float e1 = ex2(sc[j][1]);
            float e2 = ex2(sc[j][2]);
            float e3 = ex2(sc[j][3]);
            float em0 = (mw & (1u << (2 * j)))      ? e0 : 0.0f;
            float em1 = (mw & (1u << (2 * j + 1)))  ? e1 : 0.0f;
            float em2 = (mw & (1u << (16 + 2 * j))) ? e2 : 0.0f;
            float em3 = (mw & (1u << (17 + 2 * j))) ? e3 : 0.0f;
            zm0 += em0 + em1; zm1 += em2 + em3;
            pa[j >> 1][(j & 1) * 2 + 0] = h2pack(em0, em1);
            pa[j >> 1][(j & 1) * 2 + 1] = h2pack(em2, em3);
        }

        // PV: single term
        #pragma unroll
        for (int j2 = 0; j2 < 4; j2++) {
            const uint32_t vrow = (uint32_t)((j2 * 16 + ((lane >> 3) & 1) * 8 + (lane & 7)) * 72
                                             + (lane >> 4) * 8);
            #pragma unroll
            for (int ndp = 0; ndp < 4; ndp++) {
                uint32_t vh[4];
                ldsm_x4_t(vh, sb + (kvb + 4608u + vrow + (uint32_t)(ndp * 16)) * 2);
                mma16816h(Oc[ndp * 2 + 0], pa[j2], vh[0], vh[1]);
                mma16816h(Oc[ndp * 2 + 1], pa[j2], vh[2], vh[3]);
            }
        }
        __syncthreads();   // reads of buffer p done before next issue overwrites it
    }

    // quad reduce Zm (lanes sharing lane>>2 hold the same rows)
    #pragma unroll
    for (int off = 1; off < 4; off <<= 1) {
        zm0 += __shfl_xor_sync(0xffffffffu, zm0, off);
        zm1 += __shfl_xor_sync(0xffffffffu, zm1, off);
    }
    const float inv0 = 1.0f / zm0;
    const float inv1 = 1.0f / zm1;

    const int row = b * S + q0 + wid * 16 + (lane >> 2);
    #pragma unroll
    for (int nd = 0; nd < 8; nd++) {
        const int col = h * 64 + nd * 8 + (lane & 3) * 2;
        split_store_h(g_ath, g_atl, (size_t)row * D + col,
                      Oc[nd][0] * inv0, Oc[nd][1] * inv0);
        split_store_h(g_ath, g_atl, (size_t)(row + 8) * D + col,
                      Oc[nd][2] * inv1, Oc[nd][3] * inv1);
    }
}

// ---------------------------------------------------------------------------
extern "C" void kernel_launch(void* const* d_in, const int* in_sizes, int n_in,
                              void* d_out, int out_size) {
    const float* x         = (const float*)d_in[0];  // [B,S,D]
    const float* Vin       = (const float*)d_in[1];  // [B,S,H,HD]
    const float* Min       = (const float*)d_in[2];  // [B,S,S]
    const float* in_proj_w = (const float*)d_in[3];  // [3D,D]
    const float* in_proj_b = (const float*)d_in[4];  // [3D]
    const float* out_w     = (const float*)d_in[5];  // [D,D]
    const float* out_b     = (const float*)d_in[6];  // [D]
    float* out             = (float*)d_out;          // [B,S,D]

    __half *xh, *xl, *w1, *w3, *qk, *ath, *atl;
    cudaGetSymbolAddress((void**)&xh,  g_xh);
    cudaGetSymbolAddress((void**)&xl,  g_xl);
    cudaGetSymbolAddress((void**)&w1,  g_w1);
    cudaGetSymbolAddress((void**)&w3,  g_w3);
    cudaGetSymbolAddress((void**)&qk,  g_qk);
    cudaGetSymbolAddress((void**)&ath, g_ath);
    cudaGetSymbolAddress((void**)&atl, g_atl);

    cudaFuncSetAttribute(mma_gemm, cudaFuncAttributeMaxDynamicSharedMemorySize, GEMM_SMEM);
    cudaFuncSetAttribute(attn_mma, cudaFuncAttributeMaxDynamicSharedMemorySize, ATTN_SMEM);

    const int Mtot = Bsz * S;  // 4096

    // conversions + mask bit-pack
    conv_all<<<(CNT + 255) / 256, 256>>>(x, in_proj_w, out_w, Vin);
    mask_pre<<<262144 / 256, 256>>>(Min);

    // Stage 1: [Q|K] = x @ in_proj_w[0:2D]^T + b -> fp16 single (Q scaled)
    mma_gemm<<<dim3((2 * D) / 128, Mtot / 128), 256, GEMM_SMEM>>>(
        xh, xl, w1, in_proj_b, nullptr, qk, D, 2 * D, 1);

    // Stage 2: masked-renormalized attention -> fp16 hi/lo [4096][1024]
    attn_mma<<<dim3(S / 128, H, Bsz), 256, ATTN_SMEM>>>();

    // Stage 3: out = attn @ out_w^T + out_b  (fp32)
    mma_gemm<<<dim3(D / 128, Mtot / 128), 256, GEMM_SMEM>>>(
        ath, atl, w3, out_b, out, nullptr, D, D, 0);
}

// round 11
// speedup vs baseline: 2.9242x; 1.3536x over previous
#include <cuda_runtime.h>
#include <cuda_fp16.h>
#include <cstdint>

#define Bsz 2
#define S   2048
#define D   1024
#define H   16
#define HD  64

// ---------------- scratch (__device__ globals; alloc-free rule) -------------
__device__ __half g_xh[(size_t)Bsz * S * D];        // x fp16 single
__device__ __half g_w1[(size_t)2 * D * D];          // in_proj_w[0:2D] fp16 single
__device__ __half g_w3[(size_t)D * D];              // out_w fp16 single
__device__ __half g_qk[(size_t)Bsz * S * 2 * D];    // Q (scaled 0.125*log2e) | K, fp16 single
__device__ __half g_vh[(size_t)Bsz * S * D];        // V fp16 single
__device__ uint32_t g_mb[262144];                   // packed mask bits
__device__ __half g_ath[(size_t)Bsz * S * D];       // attention out fp16 single

// ---------------- helpers (all plain sm_80+ PTX; no 'a' features) -----------
__device__ __forceinline__ uint32_t smem_u32(const void* p) {
    uint32_t a;
    asm("{ .reg .u64 t; cvta.to.shared.u64 t, %1; cvt.u32.u64 %0, t; }" : "=r"(a) : "l"(p));
    return a;
}
__device__ __forceinline__ void cp16(uint32_t dst, const void* src) {
    asm volatile("cp.async.cg.shared.global [%0], [%1], 16;" :: "r"(dst), "l"(src));
}
__device__ __forceinline__ void cp_commit() {
    asm volatile("cp.async.commit_group;" ::: "memory");
}
__device__ __forceinline__ void cp_wait0() {
    asm volatile("cp.async.wait_group 0;" ::: "memory");
}
__device__ __forceinline__ void cp_wait1() {
    asm volatile("cp.async.wait_group 1;" ::: "memory");
}
__device__ __forceinline__ void ldsm_x4(uint32_t (&r)[4], uint32_t addr) {
    asm volatile("ldmatrix.sync.aligned.m8n8.x4.shared.b16 {%0,%1,%2,%3}, [%4];"
                 : "=r"(r[0]), "=r"(r[1]), "=r"(r[2]), "=r"(r[3]) : "r"(addr));
}
__device__ __forceinline__ void ldsm_x4_t(uint32_t (&r)[4], uint32_t addr) {
    asm volatile("ldmatrix.sync.aligned.m8n8.x4.trans.shared.b16 {%0,%1,%2,%3}, [%4];"
                 : "=r"(r[0]), "=r"(r[1]), "=r"(r[2]), "=r"(r[3]) : "r"(addr));
}
__device__ __forceinline__ void mma16816h(float (&c)[4], const uint32_t (&a)[4],
                                          uint32_t b0, uint32_t b1) {
    asm volatile(
        "mma.sync.aligned.m16n8k16.row.col.f32.f16.f16.f32 "
        "{%0,%1,%2,%3}, {%4,%5,%6,%7}, {%8,%9}, {%0,%1,%2,%3};"
        : "+f"(c[0]), "+f"(c[1]), "+f"(c[2]), "+f"(c[3])
        : "r"(a[0]), "r"(a[1]), "r"(a[2]), "r"(a[3]), "r"(b0), "r"(b1));
}
__device__ __forceinline__ uint32_t h2pack(float lo, float hi) {
    uint32_t r;
    asm("cvt.rn.f16x2.f32 %0, %1, %2;" : "=r"(r) : "f"(hi), "f"(lo));
    return r;
}
__device__ __forceinline__ float ex2(float x) {
    float r;
    asm("ex2.approx.f32 %0, %1;" : "=f"(r) : "f"(x));
    return r;
}
__device__ __forceinline__ void single_store_h(__half* Oh, size_t idx,
                                               float v0, float v1) {
    __half2 a; a.x = __float2half_rn(v0); a.y = __float2half_rn(v1);
    *(__half2*)(Oh + idx) = a;
}

// ---------------------------------------------------------------------------
// Fused conversions: x, w1, w3, V -> fp16 single.
// ---------------------------------------------------------------------------
#define CN1 1048576   // x  float4s
#define CN2 524288    // w1
#define CN3 262144    // w3
#define CN4 1048576   // V
#define CNT (CN1 + CN2 + CN3 + CN4)

__global__ __launch_bounds__(256)
void conv_all(const float* __restrict__ x, const float* __restrict__ w1,
              const float* __restrict__ w3, const float* __restrict__ Vin) {
    int i = blockIdx.x * 256 + threadIdx.x;
    if (i >= CNT) return;
    int j = i;
    const float* src;
    __half* o;
    if (j < CN1) { src = x; o = g_xh; }
    else if ((j -= CN1) < CN2) { src = w1; o = g_w1; }
    else if ((j -= CN2) < CN3) { src = w3; o = g_w3; }
    else { j -= CN3; src = Vin; o = g_vh; }
    float4 v = *(const float4*)(src + (size_t)j * 4);
    single_store_h(o, (size_t)j * 4, v.x, v.y);
    single_store_h(o, (size_t)j * 4 + 2, v.z, v.w);
}

// ---------------------------------------------------------------------------
// Mask bit-pack pre-pass (layout matches attention's per-thread frags):
// idx = (((b*128 + qg)*8 + r8)*32 + it)*4 + lg
// ---------------------------------------------------------------------------
__global__ __launch_bounds__(256)
void mask_pre(const float* __restrict__ Min) {
    int idx = blockIdx.x * 256 + threadIdx.x;   // 262144 total
    int lg = idx & 3, it = (idx >> 2) & 31, r8 = (idx >> 7) & 7;
    int qg = (idx >> 10) & 127, b = idx >> 17;
    const float* base = Min + ((size_t)b * S + qg * 16 + r8) * S + it * 64 + lg * 2;
    uint32_t w = 0;
    #pragma unroll
    for (int j = 0; j < 8; j++) {
        float2 a = *(const float2*)(base + j * 8);
        float2 c = *(const float2*)(base + (size_t)8 * S + j * 8);
        if (a.x != 0.f) w |= 1u << (2 * j);
        if (a.y != 0.f) w |= 1u << (2 * j + 1);
        if (c.x != 0.f) w |= 1u << (16 + 2 * j);
        if (c.y != 0.f) w |= 1u << (17 + 2 * j);
    }
    g_mb[idx] = w;
}

// ---------------------------------------------------------------------------
// fp16 single GEMM: C = A[M][K] * B[N][K]^T + bias
// 128x128 tile, BK=32, cp.async double-buffered, 8 warps (2x4).
// mode 0: fp32 out to Cf. mode 1: fp16 single out; Q cols scaled 0.125*log2e.
// smem/buf (halves): A@0, B@5120; buffer stride 10240.
// ---------------------------------------------------------------------------
#define GEMM_SMEM (2 * 10240 * 2)
#define QSC 0.1803368801111204f   // 0.125 * log2(e)

__device__ __forceinline__ void gemm_issue(
    const __half* A, const __half* Bw,
    int K, int row0, int col0, int chunk, uint32_t dstbase, int tid) {
    #pragma unroll
    for (int j = 0; j < 4; j++) {
        int linear = tid + j * 256;
        int arr = linear >> 9, rem = linear & 511;
        int r = rem >> 2, c = rem & 3;
        const __half* src = arr ? Bw : A;
        int grow = (arr ? col0 : row0) + r;
        cp16(dstbase + (uint32_t)(arr * 5120 + r * 40 + c * 8) * 2,
             src + (size_t)grow * K + chunk * 32 + c * 8);
    }
}

__global__ __launch_bounds__(256, 2)
void mma_gemm(const __half* __restrict__ A, const __half* __restrict__ Bw,
              const float* __restrict__ bias, float* __restrict__ Cf,
              __half* __restrict__ Oh, int K, int N, int mode) {
    extern __shared__ __half smem[];
    const int tid = threadIdx.x;
    const int wid = tid >> 5, lane = tid & 31;
    const int wr = wid >> 2, wc = wid & 3;
    const int row0 = blockIdx.y * 128, col0 = blockIdx.x * 128;
    const uint32_t sb = smem_u32(smem);

    float acc[4][4][4] = {};

    gemm_issue(A, Bw, K, row0, col0, 0, sb, tid);
    cp_commit();

    const int nch = K / 32;
    for (int ch = 0; ch < nch; ++ch) {
        const int p = ch & 1;
        if (ch + 1 < nch) {
            gemm_issue(A, Bw, K, row0, col0, ch + 1, sb + (p ^ 1) * 20480, tid);
            cp_commit();
            cp_wait1();
        } else {
            cp_wait0();
        }
        __syncthreads();

        const uint32_t bufb = sb + p * 20480;
        #pragma unroll
        for (int kk = 0; kk < 2; kk++) {
            const uint32_t koffs = (uint32_t)(kk * 16 + (lane >> 4) * 8);
            uint32_t b0[4], b1[4];
            ldsm_x4(b0, bufb + (5120u + (uint32_t)((wc * 32 + (lane & 15)) * 40) + koffs) * 2);
            ldsm_x4(b1, bufb + (5120u + (uint32_t)((wc * 32 + 16 + (lane & 15)) * 40) + koffs) * 2);
            #pragma unroll
            for (int i = 0; i < 4; i++) {
                uint32_t a4[4];
                ldsm_x4(a4, bufb + ((uint32_t)((wr * 64 + i * 16 + (lane & 15)) * 40) + koffs) * 2);
                mma16816h(acc[i][0], a4, b0[0], b0[2]);
                mma16816h(acc[i][1], a4, b0[1], b0[3]);
                mma16816h(acc[i][2], a4, b1[0], b1[2]);
                mma16816h(acc[i][3], a4, b1[1], b1[3]);
            }
        }
        __syncthreads();
    }

    const float qs = (mode == 1 && col0 < D) ? QSC : 1.0f;
    #pragma unroll
    for (int j = 0; j < 4; j++) {
        const int col = col0 + wc * 32 + j * 8 + (lane & 3) * 2;
        const float b0 = bias[col], b1 = bias[col + 1];
        #pragma unroll
        for (int i = 0; i < 4; i++) {
            const int row = row0 + wr * 64 + i * 16 + (lane >> 2);
            float v0 = (acc[i][j][0] + b0) * qs, v1 = (acc[i][j][1] + b1) * qs;
            float w0 = (acc[i][j][2] + b0) * qs, w1 = (acc[i][j][3] + b1) * qs;
            if (mode == 0) {
                *(float2*)(Cf + (size_t)row * N + col) = make_float2(v0, v1);
                *(float2*)(Cf + (size_t)(row + 8) * N + col) = make_float2(w0, w1);
            } else {
                single_store_h(Oh, (size_t)row * N + col, v0, v1);
                single_store_h(Oh, (size_t)(row + 8) * N + col, w0, w1);
            }
        }
    }
}

// ---------------------------------------------------------------------------
// Attention (fp16 mma, all-single). Per CTA: 128 q rows; 8 warps x 16q x 64k.
// Scores = Q·K (Q pre-scaled 0.125*log2e; e = ex2(s)); Q frags hoisted.
// PV = P·V single. Mask from packed bits. out = O / Zm (fp16 single out).
// 3-deep KV ring -> ONE barrier per iteration (write target (it+2)%3 can
// never collide with oldest reader's it%3 given barrier-enforced <=1-iter skew).
// smem halves: Q@0 (9216), 3 KV buffers @9216 stride 9216 (K@0, V@4608).
// ---------------------------------------------------------------------------
#define ATTN_SMEM ((9216 + 3 * 9216) * 2)

__device__ __forceinline__ void attn_issue_kv(int b, int h, int it, uint32_t sb,
                                              int p, int tid) {
    const int k0 = it * 64;
    #pragma unroll
    for (int j = 0; j < 4; j++) {
        int linear = tid + j * 256;
        int arr = linear >> 9, rem = linear & 511;
        int r = rem >> 3, c = rem & 7;
        const __half* src = arr
            ? g_vh + (size_t)(b * S + k0 + r) * 1024 + h * 64 + c * 8
            : g_qk + (size_t)(b * S + k0 + r) * 2048 + D + h * 64 + c * 8;
        cp16(sb + (uint32_t)(9216 + p * 9216 + arr * 4608 + r * 72 + c * 8) * 2, src);
    }
}

__global__ __launch_bounds__(256, 2)
void attn_mma() {
    extern __shared__ __half smh[];
    const int tid = threadIdx.x;
    const int wid = tid >> 5, lane = tid & 31;
    const int b = blockIdx.z, h = blockIdx.y;
    const int q0 = blockIdx.x * 128;
    const uint32_t sb = smem_u32(smh);

    // Q -> smem (same commit group as iter-0 K/V)
    #pragma unroll
    for (int j = 0; j < 4; j++) {
        int linear = tid + j * 256;
        int r = linear >> 3, c = linear & 7;
        cp16(sb + (uint32_t)(r * 72 + c * 8) * 2,
             g_qk + (size_t)(b * S + q0 + r) * 2048 + h * 64 + c * 8);
    }
    attn_issue_kv(b, h, 0, sb, 0, tid);
    cp_commit();

    float Oc[8][4] = {};
    float zm0 = 0.f, zm1 = 0.f;
    uint32_t qh[4][4];   // static Q frags, loaded once at it==0
    int p = 0;

    const uint32_t qrow_off = (uint32_t)((wid * 16 + (lane & 15)) * 72 + (lane >> 4) * 8);
    const uint32_t* mp = g_mb
        + (size_t)((b * 128 + blockIdx.x * 8 + wid) * 8 + (lane >> 2)) * 128 + (lane & 3);

    const int niter = S / 64;
    for (int it = 0; it < niter; ++it) {
        const int pn = (p + 1 == 3) ? 0 : p + 1;
        if (it + 1 < niter) {
            attn_issue_kv(b, h, it + 1, sb, pn, tid);
            cp_commit();
            cp_wait1();
        } else {
            cp_wait0();
        }

        const uint32_t mw = mp[it * 4];

        __syncthreads();   // KV buffer p (and at it=0, Q) ready; single barrier

        if (it == 0) {
            #pragma unroll
            for (int kk = 0; kk < 4; kk++)
                ldsm_x4(qh[kk], sb + (qrow_off + (uint32_t)(kk * 16)) * 2);
        }

        const uint32_t kvb = 9216u + (uint32_t)p * 9216u;

        // scores: single term Q x K
        float sc[8][4] = {};
        #pragma unroll
        for (int jp = 0; jp < 4; jp++) {
            const uint32_t krow = (uint32_t)((jp * 16 + (lane & 15)) * 72 + (lane >> 4) * 8);
            #pragma unroll
            for (int kk = 0; kk < 4; kk++) {
                uint32_t kh[4];
                ldsm_x4(kh, sb + (kvb + krow + (uint32_t)(kk * 16)) * 2);
                mma16816h(sc[jp * 2 + 0], qh[kk], kh[0], kh[2]);
                mma16816h(sc[jp * 2 + 1], qh[kk], kh[1], kh[3]);
            }
        }

        // ex2 + bit-mask + Zm + repack P (single fp16) into a-frags
        uint32_t pa[4][4];
        #pragma unroll
        for (int j = 0; j < 8; j++) {
            float e0 = ex2(sc[j][0]);
            float e1 = ex2(sc[j][1]);
            float e2 = ex2(sc[j][2]);
            float e3 = ex2(sc[j][3]);
            float em0 = (mw & (1u << (2 * j)))      ? e0 : 0.0f;
            float em1 = (mw & (1u << (2 * j + 1)))  ? e1 : 0.0f;
            float em2 = (mw & (1u << (16 + 2 * j))) ? e2 : 0.0f;
            float em3 = (mw & (1u << (17 + 2 * j))) ? e3 : 0.0f;
            zm0 += em0 + em1; zm1 += em2 + em3;
            pa[j >> 1][(j & 1) * 2 + 0] = h2pack(em0, em1);
            pa[j >> 1][(j & 1) * 2 + 1] = h2pack(em2, em3);
        }

        // PV: single term
        #pragma unroll
        for (int j2 = 0; j2 < 4; j2++) {
            const uint32_t vrow = (uint32_t)((j2 * 16 + ((lane >> 3) & 1) * 8 + (lane & 7)) * 72
                                             + (lane >> 4) * 8);
            #pragma unroll
            for (int ndp = 0; ndp < 4; ndp++) {
                uint32_t vh[4];
                ldsm_x4_t(vh, sb + (kvb + 4608u + vrow + (uint32_t)(ndp * 16)) * 2);
                mma16816h(Oc[ndp * 2 + 0], pa[j2], vh[0], vh[1]);
                mma16816h(Oc[ndp * 2 + 1], pa[j2], vh[2], vh[3]);
            }
        }
        p = pn;
    }

    // quad reduce Zm (lanes sharing lane>>2 hold the same rows)
    #pragma unroll
    for (int off = 1; off < 4; off <<= 1) {
        zm0 += __shfl_xor_sync(0xffffffffu, zm0, off);
        zm1 += __shfl_xor_sync(0xffffffffu, zm1, off);
    }
    const float inv0 = 1.0f / zm0;
    const float inv1 = 1.0f / zm1;

    const int row = b * S + q0 + wid * 16 + (lane >> 2);
    #pragma unroll
    for (int nd = 0; nd < 8; nd++) {
        const int col = h * 64 + nd * 8 + (lane & 3) * 2;
        single_store_h(g_ath, (size_t)row * D + col,
                       Oc[nd][0] * inv0, Oc[nd][1] * inv0);
        single_store_h(g_ath, (size_t)(row + 8) * D + col,
                       Oc[nd][2] * inv1, Oc[nd][3] * inv1);
    }
}

// ---------------------------------------------------------------------------
extern "C" void kernel_launch(void* const* d_in, const int* in_sizes, int n_in,
                              void* d_out, int out_size) {
    const float* x         = (const float*)d_in[0];  // [B,S,D]
    const float* Vin       = (const float*)d_in[1];  // [B,S,H,HD]
    const float* Min       = (const float*)d_in[2];  // [B,S,S]
    const float* in_proj_w = (const float*)d_in[3];  // [3D,D]
    const float* in_proj_b = (const float*)d_in[4];  // [3D]
    const float* out_w     = (const float*)d_in[5];  // [D,D]
    const float* out_b     = (const float*)d_in[6];  // [D]
    float* out             = (float*)d_out;          // [B,S,D]

    __half *xh, *w1, *w3, *qk, *ath;
    cudaGetSymbolAddress((void**)&xh,  g_xh);
    cudaGetSymbolAddress((void**)&w1,  g_w1);
    cudaGetSymbolAddress((void**)&w3,  g_w3);
    cudaGetSymbolAddress((void**)&qk,  g_qk);
    cudaGetSymbolAddress((void**)&ath, g_ath);

    cudaFuncSetAttribute(mma_gemm, cudaFuncAttributeMaxDynamicSharedMemorySize, GEMM_SMEM);
    cudaFuncSetAttribute(attn_mma, cudaFuncAttributeMaxDynamicSharedMemorySize, ATTN_SMEM);

    const int Mtot = Bsz * S;  // 4096

    // conversions + mask bit-pack
    conv_all<<<(CNT + 255) / 256, 256>>>(x, in_proj_w, out_w, Vin);
    mask_pre<<<262144 / 256, 256>>>(Min);

    // Stage 1: [Q|K] = x @ in_proj_w[0:2D]^T + b -> fp16 single (Q scaled)
    mma_gemm<<<dim3((2 * D) / 128, Mtot / 128), 256, GEMM_SMEM>>>(
        xh, w1, in_proj_b, nullptr, qk, D, 2 * D, 1);

    // Stage 2: masked-renormalized attention -> fp16 single [4096][1024]
    attn_mma<<<dim3(S / 128, H, Bsz), 256, ATTN_SMEM>>>();

    // Stage 3: out = attn @ out_w^T + out_b  (fp32)
    mma_gemm<<<dim3(D / 128, Mtot / 128), 256, GEMM_SMEM>>>(
        ath, w3, out_b, out, nullptr, D, D, 0);
}